// round 6
// baseline (speedup 1.0000x reference)
#include <cuda_runtime.h>
#include <cuda_bf16.h>
#include <cstdint>
#include <math.h>

#define NN    32
#define BSZv  512
#define NE    7
#define DIN   512
#define DHv   256
#define RHv   64
#define NPAIR 21
#define M_ROWS (NN * BSZv * NE)   // 114688
#define NCFG  128

// ---------------- scratch (device globals; no allocation allowed) ------------
__device__ __align__(128) __nv_bfloat16 g_w0p[(size_t)(DIN / 32) * DHv * 64];
__device__ __align__(128) __nv_bfloat16 g_w1p[(size_t)(DHv / 32) * DHv * 64];
__device__ __align__(128) __nv_bfloat16 g_h1p[(size_t)(DHv / 32) * M_ROWS * 64];
__device__ float g_un[(size_t)M_ROWS * 2];
__device__ float g_pairsum[(size_t)BSZv * NCFG];

// ---------------- PTX helpers ------------------------------------------------
__device__ __forceinline__ uint32_t smem_u32(const void* p) {
    uint32_t a;
    asm("{ .reg .u64 t; cvta.to.shared.u64 t, %1; cvt.u32.u64 %0, t; }" : "=r"(a) : "l"(p));
    return a;
}
__device__ __forceinline__ void ldsm4(uint32_t a, uint32_t* r) {
    asm volatile("ldmatrix.sync.aligned.m8n8.x4.shared.b16 {%0,%1,%2,%3}, [%4];"
                 : "=r"(r[0]), "=r"(r[1]), "=r"(r[2]), "=r"(r[3]) : "r"(a));
}
__device__ __forceinline__ void mma_bf16(float* c, const uint32_t* a, uint32_t b0, uint32_t b1) {
    asm volatile("mma.sync.aligned.m16n8k16.row.col.f32.bf16.bf16.f32 "
                 "{%0,%1,%2,%3}, {%4,%5,%6,%7}, {%8,%9}, {%0,%1,%2,%3};"
                 : "+f"(c[0]), "+f"(c[1]), "+f"(c[2]), "+f"(c[3])
                 : "r"(a[0]), "r"(a[1]), "r"(a[2]), "r"(a[3]), "r"(b0), "r"(b1));
}
#define CP16(dst, src) asm volatile("cp.async.cg.shared.global [%0], [%1], 16;" :: "r"(dst), "l"(src))
#define CPCOMMIT()     asm volatile("cp.async.commit_group;" ::: "memory")
#define CPWAIT0()      asm volatile("cp.async.wait_group 0;" ::: "memory")
#define CPWAIT1()      asm volatile("cp.async.wait_group 1;" ::: "memory")
#define STS128(a, v0, v1, v2, v3) \
    asm volatile("st.shared.v4.b32 [%0], {%1,%2,%3,%4};" :: "r"(a), "r"(v0), "r"(v1), "r"(v2), "r"(v3))

__device__ __forceinline__ uint32_t pack2(__nv_bfloat16 a, __nv_bfloat16 b) {
    __nv_bfloat162 t = __halves2bfloat162(a, b);
    return *reinterpret_cast<uint32_t*>(&t);
}
__device__ __forceinline__ void split2(float a, float b, uint32_t& h, uint32_t& l) {
    __nv_bfloat16 ha = __float2bfloat16_rn(a), hb = __float2bfloat16_rn(b);
    __nv_bfloat16 la = __float2bfloat16_rn(a - __bfloat162float(ha));
    __nv_bfloat16 lb = __float2bfloat16_rn(b - __bfloat162float(hb));
    h = pack2(ha, hb);
    l = pack2(la, lb);
}

// ---------------- weight packing ----------------------------------------------
__global__ __launch_bounds__(256) void pack_weights(
    const float* __restrict__ W, __nv_bfloat16* __restrict__ dst, int K)
{
    int idx = blockIdx.x * 256 + threadIdx.x;
    if (idx >= K * 256) return;
    int k = idx >> 8, n = idx & 255;
    float v = W[idx];
    __nv_bfloat16 h = __float2bfloat16_rn(v);
    __nv_bfloat16 l = __float2bfloat16_rn(v - __bfloat162float(h));
    size_t o = ((size_t)(k >> 5) * 256 + n) * 64 + (k & 31);
    dst[o] = h;
    dst[o + 32] = l;
}

// ---------------- GEMM (mma.sync bf16x3, term-reordered) ----------------------
#define NSTAGE   3
#define STAGE_SZ 32768
#define SM_BIAS  (NSTAGE * STAGE_SZ)
#define SM_W2    (SM_BIAS + 512)
#define SMEM_SZ  (SM_W2 + 1024)

template <int KDIM, int MODE>
__global__ __launch_bounds__(256, 2) void gemm_tc(
    const float* __restrict__ Af, const __nv_bfloat16* __restrict__ Ap,
    const __nv_bfloat16* __restrict__ Wp, const float* __restrict__ bias,
    const float* __restrict__ W2, __nv_bfloat16* __restrict__ outp,
    float* __restrict__ un)
{
    extern __shared__ char smem[];
    constexpr int NC = KDIM / 32;
    const int tid = threadIdx.x;
    const int lane = tid & 31;
    const int wid = tid >> 5;
    const int warp_m = wid >> 2, warp_n = wid & 3;
    const int nBase = blockIdx.x * 128;
    const size_t mBase = (size_t)blockIdx.y * 128;

    const uint32_t sb = smem_u32(smem);
    float* biasS = (float*)(smem + SM_BIAS);
    float* W2s = (float*)(smem + SM_W2);
    if (tid < 128) biasS[tid] = bias[nBase + tid];
    if (MODE == 1) W2s[tid] = W2[nBase * 2 + tid];

    const int crow = tid >> 1;
    const int chalf = tid & 1;
    const int cxor = crow & 7;

    const uint32_t aRowOff = (uint32_t)(warp_m * 64 + (lane & 15)) * 128;
    const uint32_t aKsel = (uint32_t)(lane >> 4);
    const uint32_t bRowOff = (uint32_t)(warp_n * 32 + ((lane >> 4) << 3) + (lane & 7)) * 128;
    const uint32_t bKsel = (uint32_t)((lane >> 3) & 1);
    const uint32_t xr = (uint32_t)(lane & 7);

    float acc[4][4][4];
#pragma unroll
    for (int a = 0; a < 4; a++)
#pragma unroll
        for (int b = 0; b < 4; b++)
#pragma unroll
            for (int q = 0; q < 4; q++) acc[a][b][q] = 0.f;

    float rA[16];   // MODE0 staging

    auto loadA_regs = [&](int c) {
        const float* p = Af + (mBase + crow) * KDIM + c * 32 + chalf * 16;
        *(float4*)(rA)      = *(const float4*)(p);
        *(float4*)(rA + 4)  = *(const float4*)(p + 4);
        *(float4*)(rA + 8)  = *(const float4*)(p + 8);
        *(float4*)(rA + 12) = *(const float4*)(p + 12);
    };
    auto storeA_regs = [&](int stg) {
        uint32_t dst = sb + stg * STAGE_SZ + crow * 128;
        uint32_t hh[8], ll[8];
#pragma unroll
        for (int q = 0; q < 8; q++) split2(rA[2 * q], rA[2 * q + 1], hh[q], ll[q]);
        STS128(dst + ((chalf * 2 + 0) ^ cxor) * 16, hh[0], hh[1], hh[2], hh[3]);
        STS128(dst + ((chalf * 2 + 1) ^ cxor) * 16, hh[4], hh[5], hh[6], hh[7]);
        STS128(dst + ((4 + chalf * 2 + 0) ^ cxor) * 16, ll[0], ll[1], ll[2], ll[3]);
        STS128(dst + ((4 + chalf * 2 + 1) ^ cxor) * 16, ll[4], ll[5], ll[6], ll[7]);
    };
    auto cpA = [&](int c, int stage) {
        const char* src = (const char*)(Ap + ((size_t)c * M_ROWS + mBase + crow) * 64 + chalf * 32);
        uint32_t dst = sb + stage * STAGE_SZ + crow * 128;
#pragma unroll
        for (int j = 0; j < 4; j++)
            CP16(dst + ((chalf * 4 + j) ^ cxor) * 16, src + j * 16);
    };
    auto cpB = [&](int c, int stage) {
        const char* src = (const char*)(Wp + ((size_t)c * 256 + nBase + crow) * 64 + chalf * 32);
        uint32_t dst = sb + stage * STAGE_SZ + 16384 + crow * 128;
#pragma unroll
        for (int j = 0; j < 4; j++)
            CP16(dst + ((chalf * 4 + j) ^ cxor) * 16, src + j * 16);
    };

    // Term-reordered compute: same-accumulator MMA reuse distance 16 (MODE1) / 8 (MODE0)
    auto compute = [&](int stage) {
        uint32_t Ab = sb + stage * STAGE_SZ + aRowOff;
        uint32_t Bb = sb + stage * STAGE_SZ + 16384 + bRowOff;
#pragma unroll
        for (int s = 0; s < 2; s++) {
            uint32_t bh[8], bl[8];
#pragma unroll
            for (int nb = 0; nb < 2; nb++) {
                ldsm4(Bb + nb * 2048 + (((s * 2 + bKsel)) ^ xr) * 16, bh + 4 * nb);
                ldsm4(Bb + nb * 2048 + ((4 + s * 2 + bKsel) ^ xr) * 16, bl + 4 * nb);
            }
            if (MODE == 1) {
                // all 4 mi fragments live: 32 frag regs, 48 MMAs with distance 16
                uint32_t ah[16], al[16];
#pragma unroll
                for (int mi = 0; mi < 4; mi++) {
                    ldsm4(Ab + mi * 2048 + (((s * 2 + aKsel)) ^ xr) * 16, ah + 4 * mi);
                    ldsm4(Ab + mi * 2048 + ((4 + s * 2 + aKsel) ^ xr) * 16, al + 4 * mi);
                }
#pragma unroll
                for (int mi = 0; mi < 4; mi++)
#pragma unroll
                    for (int nj = 0; nj < 4; nj++)
                        mma_bf16(acc[mi][nj], ah + 4 * mi, bh[2 * nj], bh[2 * nj + 1]);
#pragma unroll
                for (int mi = 0; mi < 4; mi++)
#pragma unroll
                    for (int nj = 0; nj < 4; nj++)
                        mma_bf16(acc[mi][nj], ah + 4 * mi, bl[2 * nj], bl[2 * nj + 1]);
#pragma unroll
                for (int mi = 0; mi < 4; mi++)
#pragma unroll
                    for (int nj = 0; nj < 4; nj++)
                        mma_bf16(acc[mi][nj], al + 4 * mi, bh[2 * nj], bh[2 * nj + 1]);
            } else {
                // 2-mi pairs: 16 frag regs (rA also live), distance 8
#pragma unroll
                for (int mp = 0; mp < 2; mp++) {
                    uint32_t ah[8], al[8];
#pragma unroll
                    for (int q = 0; q < 2; q++) {
                        int mi = mp * 2 + q;
                        ldsm4(Ab + mi * 2048 + (((s * 2 + aKsel)) ^ xr) * 16, ah + 4 * q);
                        ldsm4(Ab + mi * 2048 + ((4 + s * 2 + aKsel) ^ xr) * 16, al + 4 * q);
                    }
#pragma unroll
                    for (int q = 0; q < 2; q++)
#pragma unroll
                        for (int nj = 0; nj < 4; nj++)
                            mma_bf16(acc[mp * 2 + q][nj], ah + 4 * q, bh[2 * nj], bh[2 * nj + 1]);
#pragma unroll
                    for (int q = 0; q < 2; q++)
#pragma unroll
                        for (int nj = 0; nj < 4; nj++)
                            mma_bf16(acc[mp * 2 + q][nj], ah + 4 * q, bl[2 * nj], bl[2 * nj + 1]);
#pragma unroll
                    for (int q = 0; q < 2; q++)
#pragma unroll
                        for (int nj = 0; nj < 4; nj++)
                            mma_bf16(acc[mp * 2 + q][nj], al + 4 * q, bh[2 * nj], bh[2 * nj + 1]);
                }
            }
        }
    };

    // ---- prologue: prefetch chunks 0 and 1 ----
    if (MODE == 0) {
        cpB(0, 0); CPCOMMIT();
        cpB(1, 1); CPCOMMIT();
        loadA_regs(0);
        storeA_regs(0);
        loadA_regs(1);
    } else {
        cpA(0, 0); cpB(0, 0); CPCOMMIT();
        cpA(1, 1); cpB(1, 1); CPCOMMIT();
    }

    // ---- main loop: 3-stage, prefetch 2 ahead ----
    for (int c = 0; c < NC; c++) {
        const int stg = c % NSTAGE;
        if (c + 2 <= NC) CPWAIT1(); else CPWAIT0();
        __syncthreads();
        if (MODE == 0) {
            if (c + 2 < NC) { cpB(c + 2, (c + 2) % NSTAGE); CPCOMMIT(); }
            compute(stg);
            if (c + 1 < NC) {
                storeA_regs((c + 1) % NSTAGE);
                if (c + 2 < NC) loadA_regs(c + 2);
            }
        } else {
            if (c + 2 < NC) { cpA(c + 2, (c + 2) % NSTAGE); cpB(c + 2, (c + 2) % NSTAGE); CPCOMMIT(); }
            compute(stg);
        }
    }

    // ---- epilogue ----
    const int rloc = warp_m * 64 + (lane >> 2);
    const int nl0 = warp_n * 32 + (lane & 3) * 2;

    if (MODE == 0) {
#pragma unroll
        for (int mi = 0; mi < 4; mi++)
#pragma unroll
            for (int nj = 0; nj < 4; nj++) {
                int nl = nl0 + nj * 8;
                float b0v = biasS[nl], b1v = biasS[nl + 1];
                float v00 = fmaxf(acc[mi][nj][0] + b0v, 0.f);
                float v01 = fmaxf(acc[mi][nj][1] + b1v, 0.f);
                float v10 = fmaxf(acc[mi][nj][2] + b0v, 0.f);
                float v11 = fmaxf(acc[mi][nj][3] + b1v, 0.f);
                int gn = nBase + nl;
                int cpk = gn >> 5, slot = gn & 31;
                size_t r0 = mBase + rloc + mi * 16;
                size_t o0 = ((size_t)cpk * M_ROWS + r0) * 64 + slot;
                size_t o1 = o0 + 8 * 64;
                uint32_t h, l;
                split2(v00, v01, h, l);
                *(uint32_t*)(outp + o0) = h;
                *(uint32_t*)(outp + o0 + 32) = l;
                split2(v10, v11, h, l);
                *(uint32_t*)(outp + o1) = h;
                *(uint32_t*)(outp + o1 + 32) = l;
            }
    } else {
        float up[16];
#pragma unroll
        for (int i = 0; i < 16; i++) up[i] = 0.f;
#pragma unroll
        for (int mi = 0; mi < 4; mi++)
#pragma unroll
            for (int nj = 0; nj < 4; nj++) {
                int nl = nl0 + nj * 8;
                float b0v = biasS[nl], b1v = biasS[nl + 1];
                float w00 = W2s[2 * nl], w01 = W2s[2 * nl + 1];
                float w10 = W2s[2 * nl + 2], w11 = W2s[2 * nl + 3];
                float v00 = fmaxf(acc[mi][nj][0] + b0v, 0.f);
                float v01 = fmaxf(acc[mi][nj][1] + b1v, 0.f);
                float v10 = fmaxf(acc[mi][nj][2] + b0v, 0.f);
                float v11 = fmaxf(acc[mi][nj][3] + b1v, 0.f);
                up[mi * 4 + 0] += v00 * w00 + v01 * w10;
                up[mi * 4 + 1] += v00 * w01 + v01 * w11;
                up[mi * 4 + 2] += v10 * w00 + v11 * w10;
                up[mi * 4 + 3] += v10 * w01 + v11 * w11;
            }
#pragma unroll
        for (int k = 1; k <= 2; k <<= 1)
#pragma unroll
            for (int i = 0; i < 16; i++)
                up[i] += __shfl_xor_sync(0xffffffffu, up[i], k);
        if ((lane & 3) == 0) {
#pragma unroll
            for (int mi = 0; mi < 4; mi++) {
                size_t r0 = mBase + rloc + mi * 16;
                size_t r1 = r0 + 8;
                atomicAdd(&un[r0 * 2 + 0], up[mi * 4 + 0]);
                atomicAdd(&un[r0 * 2 + 1], up[mi * 4 + 1]);
                atomicAdd(&un[r1 * 2 + 0], up[mi * 4 + 2]);
                atomicAdd(&un[r1 * 2 + 1], up[mi * 4 + 3]);
            }
        }
    }
}

// -------- binary MLP + pairwise config sums ----------------------------------
__global__ __launch_bounds__(128) void binary_kernel(
    const float* __restrict__ ctx, const float* __restrict__ R0,
    const float* __restrict__ r0, const float* __restrict__ R1,
    const float* __restrict__ r1, float* __restrict__ pairsum)
{
    __shared__ float cd[NPAIR][5];
    __shared__ float R0s[5][RHv];
    __shared__ float r0s[RHv];
    __shared__ float R1s[RHv][3];
    __shared__ float r1s[3];
    __shared__ float h2s[NPAIR][RHv];
    __shared__ float bp4s[NPAIR][4];

    int b = blockIdx.x, t = threadIdx.x;
    for (int i = t; i < NPAIR * 5; i += 128) cd[i / 5][i % 5] = ctx[b * NPAIR * 5 + i];
    for (int i = t; i < 5 * RHv; i += 128) R0s[i / RHv][i % RHv] = R0[i];
    if (t < RHv) r0s[t] = r0[t];
    for (int i = t; i < RHv * 3; i += 128) R1s[i / 3][i % 3] = R1[i];
    if (t < 3) r1s[t] = r1[t];
    __syncthreads();

    for (int idx = t; idx < NPAIR * RHv; idx += 128) {
        int p = idx / RHv, u = idx % RHv;
        float v = r0s[u];
#pragma unroll
        for (int x = 0; x < 5; x++) v += cd[p][x] * R0s[x][u];
        h2s[p][u] = fmaxf(v, 0.f);
    }
    __syncthreads();

    if (t < NPAIR * 3) {
        int p = t / 3, y = t % 3;
        float v = r1s[y];
#pragma unroll
        for (int u = 0; u < RHv; u++) v += h2s[p][u] * R1s[u][y];
        if (y == 0) bp4s[p][0] = v;
        else if (y == 1) { bp4s[p][1] = v; bp4s[p][2] = v; }
        else bp4s[p][3] = v;
    }
    __syncthreads();

    int s = t;
    float accv = 0.f;
    int p = 0;
#pragma unroll
    for (int i = 0; i < NE; i++)
#pragma unroll
        for (int j = i + 1; j < NE; j++) {
            int bi = (s >> (6 - i)) & 1;
            int bj = (s >> (6 - j)) & 1;
            accv += bp4s[p][bi * 2 + bj];
            p++;
        }
    pairsum[(size_t)b * NCFG + s] = accv;
}

// ---------------- joint + lse + marginals: one warp per (n,b) -----------------
__global__ __launch_bounds__(256) void joint_kernel(
    const float* __restrict__ un, const float* __restrict__ ps,
    const float* __restrict__ b2v, float* __restrict__ out_marg,
    float* __restrict__ out_joint)
{
    int w = blockIdx.x * 8 + (threadIdx.x >> 5);
    int lane = threadIdx.x & 31;
    int b = w & (BSZv - 1), n = w >> 9;
    size_t nb = (size_t)n * BSZv + b;

    float val = 0.f;
    if (lane < 14) val = un[nb * 14 + lane] + b2v[lane & 1];
    float u[14];
#pragma unroll
    for (int i = 0; i < 14; i++) u[i] = __shfl_sync(0xffffffffu, val, i);

    float j[4], e[4];
    float mx = -1e30f;
#pragma unroll
    for (int q = 0; q < 4; q++) {
        int s = q * 32 + lane;
        float t = ps[(size_t)b * NCFG + s];
#pragma unroll
        for (int i = 0; i < NE; i++) t += u[i * 2 + ((s >> (6 - i)) & 1)];
        j[q] = t;
        mx = fmaxf(mx, t);
    }
#pragma unroll
    for (int o = 16; o; o >>= 1) mx = fmaxf(mx, __shfl_xor_sync(0xffffffffu, mx, o));

    float p1[NE], p0[NE];
#pragma unroll
    for (int i = 0; i < NE; i++) { p1[i] = 0.f; p0[i] = 0.f; }
#pragma unroll
    for (int q = 0; q < 4; q++) {
        int s = q * 32 + lane;
        e[q] = __expf(j[q] - mx);
#pragma unroll
        for (int i = 0; i < NE; i++) {
            if ((s >> (6 - i)) & 1) p1[i] += e[q];
            else p0[i] += e[q];
        }
    }
#pragma unroll
    for (int o = 16; o; o >>= 1)
#pragma unroll
        for (int i = 0; i < NE; i++) {
            p1[i] += __shfl_xor_sync(0xffffffffu, p1[i], o);
            p0[i] += __shfl_xor_sync(0xffffffffu, p0[i], o);
        }

    float lt = __logf(p1[0] + p0[0]);
#pragma unroll
    for (int q = 0; q < 4; q++)
        out_joint[nb * NCFG + q * 32 + lane] = j[q] - mx - lt;
    if (lane < NE)
        out_marg[nb * NE + lane] = __logf(p1[lane]) - __logf(p0[lane]);
}

// ---------------- launch -------------------------------------------------------
extern "C" void kernel_launch(void* const* d_in, const int* in_sizes, int n_in,
                              void* d_out, int out_size)
{
    const float* input = (const float*)d_in[0];
    const float* ctx   = (const float*)d_in[1];
    const float* W0 = (const float*)d_in[4];
    const float* b0 = (const float*)d_in[5];
    const float* W1 = (const float*)d_in[6];
    const float* b1 = (const float*)d_in[7];
    const float* W2 = (const float*)d_in[8];
    const float* b2 = (const float*)d_in[9];
    const float* R0 = (const float*)d_in[10];
    const float* r0 = (const float*)d_in[11];
    const float* R1 = (const float*)d_in[12];
    const float* r1 = (const float*)d_in[13];

    float* out = (float*)d_out;
    float* out_marg = out;
    float* out_joint = out + (size_t)M_ROWS;

    __nv_bfloat16 *w0p, *w1p, *h1p;
    float *un, *psum;
    cudaGetSymbolAddress((void**)&w0p, g_w0p);
    cudaGetSymbolAddress((void**)&w1p, g_w1p);
    cudaGetSymbolAddress((void**)&h1p, g_h1p);
    cudaGetSymbolAddress((void**)&un, g_un);
    cudaGetSymbolAddress((void**)&psum, g_pairsum);

    cudaFuncSetAttribute(gemm_tc<DIN, 0>, cudaFuncAttributeMaxDynamicSharedMemorySize, SMEM_SZ);
    cudaFuncSetAttribute(gemm_tc<DHv, 1>, cudaFuncAttributeMaxDynamicSharedMemorySize, SMEM_SZ);

    pack_weights<<<DIN, 256>>>(W0, w0p, DIN);
    pack_weights<<<DHv, 256>>>(W1, w1p, DHv);
    cudaMemsetAsync(un, 0, (size_t)M_ROWS * 2 * sizeof(float));

    gemm_tc<DIN, 0><<<dim3(2, M_ROWS / 128), 256, SMEM_SZ>>>(
        input, nullptr, w0p, b0, nullptr, h1p, nullptr);
    gemm_tc<DHv, 1><<<dim3(2, M_ROWS / 128), 256, SMEM_SZ>>>(
        nullptr, h1p, w1p, b1, W2, nullptr, un);
    binary_kernel<<<BSZv, 128>>>(ctx, R0, r0, R1, r1, psum);
    joint_kernel<<<(NN * BSZv) / 8, 256>>>(un, psum, b2, out_marg, out_joint);
}

// round 7
// speedup vs baseline: 1.0148x; 1.0148x over previous
#include <cuda_runtime.h>
#include <cuda_bf16.h>
#include <cstdint>
#include <math.h>

#define NN    32
#define BSZv  512
#define NE    7
#define DIN   512
#define DHv   256
#define RHv   64
#define NPAIR 21
#define M_ROWS (NN * BSZv * NE)   // 114688
#define NCFG  128
#define NTILES 1792               // (M_ROWS/128) * 2 n-halves
#define PGRID  304                // 152 SMs * 2 CTAs

// ---------------- scratch (device globals; no allocation allowed) ------------
__device__ __align__(128) __nv_bfloat16 g_w0p[(size_t)(DIN / 32) * DHv * 64];
__device__ __align__(128) __nv_bfloat16 g_w1p[(size_t)(DHv / 32) * DHv * 64];
__device__ __align__(128) __nv_bfloat16 g_h1p[(size_t)(DHv / 32) * M_ROWS * 64];
__device__ float g_un[(size_t)M_ROWS * 2];
__device__ float g_pairsum[(size_t)BSZv * NCFG];

// ---------------- PTX helpers ------------------------------------------------
__device__ __forceinline__ uint32_t smem_u32(const void* p) {
    uint32_t a;
    asm("{ .reg .u64 t; cvta.to.shared.u64 t, %1; cvt.u32.u64 %0, t; }" : "=r"(a) : "l"(p));
    return a;
}
__device__ __forceinline__ void ldsm4(uint32_t a, uint32_t* r) {
    asm volatile("ldmatrix.sync.aligned.m8n8.x4.shared.b16 {%0,%1,%2,%3}, [%4];"
                 : "=r"(r[0]), "=r"(r[1]), "=r"(r[2]), "=r"(r[3]) : "r"(a));
}
__device__ __forceinline__ void mma_bf16(float* c, const uint32_t* a, uint32_t b0, uint32_t b1) {
    asm volatile("mma.sync.aligned.m16n8k16.row.col.f32.bf16.bf16.f32 "
                 "{%0,%1,%2,%3}, {%4,%5,%6,%7}, {%8,%9}, {%0,%1,%2,%3};"
                 : "+f"(c[0]), "+f"(c[1]), "+f"(c[2]), "+f"(c[3])
                 : "r"(a[0]), "r"(a[1]), "r"(a[2]), "r"(a[3]), "r"(b0), "r"(b1));
}
#define CP16(dst, src) asm volatile("cp.async.cg.shared.global [%0], [%1], 16;" :: "r"(dst), "l"(src))
#define CPCOMMIT()     asm volatile("cp.async.commit_group;" ::: "memory")
#define CPWAIT1()      asm volatile("cp.async.wait_group 1;" ::: "memory")
#define STS128(a, v0, v1, v2, v3) \
    asm volatile("st.shared.v4.b32 [%0], {%1,%2,%3,%4};" :: "r"(a), "r"(v0), "r"(v1), "r"(v2), "r"(v3))

__device__ __forceinline__ uint32_t pack2(__nv_bfloat16 a, __nv_bfloat16 b) {
    __nv_bfloat162 t = __halves2bfloat162(a, b);
    return *reinterpret_cast<uint32_t*>(&t);
}
__device__ __forceinline__ void split2(float a, float b, uint32_t& h, uint32_t& l) {
    __nv_bfloat16 ha = __float2bfloat16_rn(a), hb = __float2bfloat16_rn(b);
    __nv_bfloat16 la = __float2bfloat16_rn(a - __bfloat162float(ha));
    __nv_bfloat16 lb = __float2bfloat16_rn(b - __bfloat162float(hb));
    h = pack2(ha, hb);
    l = pack2(la, lb);
}

// ---------------- weight packing ----------------------------------------------
__global__ __launch_bounds__(256) void pack_weights(
    const float* __restrict__ W, __nv_bfloat16* __restrict__ dst, int K)
{
    int idx = blockIdx.x * 256 + threadIdx.x;
    if (idx >= K * 256) return;
    int k = idx >> 8, n = idx & 255;
    float v = W[idx];
    __nv_bfloat16 h = __float2bfloat16_rn(v);
    __nv_bfloat16 l = __float2bfloat16_rn(v - __bfloat162float(h));
    size_t o = ((size_t)(k >> 5) * 256 + n) * 64 + (k & 31);
    dst[o] = h;
    dst[o + 32] = l;
}

// ---------------- GEMM (mma.sync bf16x3, persistent continuous pipeline) -----
// tile t: mBase = (t>>1)*128, nBase = (t&1)*128. Stream s = tileIdx*NC + chunk.
#define NSTAGE   3
#define STAGE_SZ 32768
#define SM_BIAS  (NSTAGE * STAGE_SZ)          // 256 f32 (full width)
#define SM_W2    (SM_BIAS + 1024)             // 512 f32 (full width)
#define SMEM_SZ  (SM_W2 + 2048)

template <int KDIM, int MODE>
__global__ __launch_bounds__(256, 2) void gemm_tc(
    const float* __restrict__ Af, const __nv_bfloat16* __restrict__ Ap,
    const __nv_bfloat16* __restrict__ Wp, const float* __restrict__ bias,
    const float* __restrict__ W2, __nv_bfloat16* __restrict__ outp,
    float* __restrict__ un)
{
    extern __shared__ char smem[];
    constexpr int NC = KDIM / 32;
    const int tid = threadIdx.x;
    const int lane = tid & 31;
    const int wid = tid >> 5;
    const int warp_m = wid >> 2, warp_n = wid & 3;
    const int bid = blockIdx.x;
    const int GRID = gridDim.x;

    const uint32_t sb = smem_u32(smem);
    float* biasS = (float*)(smem + SM_BIAS);
    float* W2s = (float*)(smem + SM_W2);
    biasS[tid] = bias[tid];                                // full 256
    if (MODE == 1) { W2s[tid] = W2[tid]; W2s[tid + 256] = W2[tid + 256]; }

    const int crow = tid >> 1;
    const int chalf = tid & 1;
    const int cxor = crow & 7;

    const uint32_t aRowOff = (uint32_t)(warp_m * 64 + (lane & 15)) * 128;
    const uint32_t aKsel = (uint32_t)(lane >> 4);
    const uint32_t bRowOff = (uint32_t)(warp_n * 32 + ((lane >> 4) << 3) + (lane & 7)) * 128;
    const uint32_t bKsel = (uint32_t)((lane >> 3) & 1);
    const uint32_t xr = (uint32_t)(lane & 7);

    const int myTiles = (NTILES - bid + GRID - 1) / GRID;
    const int total = myTiles * NC;

    float acc[4][4][4];
#pragma unroll
    for (int a = 0; a < 4; a++)
#pragma unroll
        for (int b = 0; b < 4; b++)
#pragma unroll
            for (int q = 0; q < 4; q++) acc[a][b][q] = 0.f;

    float rA[16];   // MODE0 staging

    // stream -> addressing
    auto loadA_regs = [&](int s) {            // MODE0 only
        int i = s / NC, c = s % NC;
        int t = bid + i * GRID;
        size_t mB = (size_t)(t >> 1) * 128;
        const float* p = Af + (mB + crow) * KDIM + c * 32 + chalf * 16;
        *(float4*)(rA)      = *(const float4*)(p);
        *(float4*)(rA + 4)  = *(const float4*)(p + 4);
        *(float4*)(rA + 8)  = *(const float4*)(p + 8);
        *(float4*)(rA + 12) = *(const float4*)(p + 12);
    };
    auto storeA_regs = [&](int stg) {
        uint32_t dst = sb + stg * STAGE_SZ + crow * 128;
        uint32_t hh[8], ll[8];
#pragma unroll
        for (int q = 0; q < 8; q++) split2(rA[2 * q], rA[2 * q + 1], hh[q], ll[q]);
        STS128(dst + ((chalf * 2 + 0) ^ cxor) * 16, hh[0], hh[1], hh[2], hh[3]);
        STS128(dst + ((chalf * 2 + 1) ^ cxor) * 16, hh[4], hh[5], hh[6], hh[7]);
        STS128(dst + ((4 + chalf * 2 + 0) ^ cxor) * 16, ll[0], ll[1], ll[2], ll[3]);
        STS128(dst + ((4 + chalf * 2 + 1) ^ cxor) * 16, ll[4], ll[5], ll[6], ll[7]);
    };
    // prefetch B (and A for MODE1) for stream s; ALWAYS commits a group
    auto prefetch = [&](int s) {
        if (s < total) {
            int i = s / NC, c = s % NC;
            int t = bid + i * GRID;
            int stage = s % NSTAGE;
            int nB = (t & 1) * 128;
            if (MODE == 1) {
                size_t mB = (size_t)(t >> 1) * 128;
                const char* srcA = (const char*)(Ap + ((size_t)c * M_ROWS + mB + crow) * 64 + chalf * 32);
                uint32_t dstA = sb + stage * STAGE_SZ + crow * 128;
#pragma unroll
                for (int j = 0; j < 4; j++)
                    CP16(dstA + ((chalf * 4 + j) ^ cxor) * 16, srcA + j * 16);
            }
            const char* srcB = (const char*)(Wp + ((size_t)c * 256 + nB + crow) * 64 + chalf * 32);
            uint32_t dstB = sb + stage * STAGE_SZ + 16384 + crow * 128;
#pragma unroll
            for (int j = 0; j < 4; j++)
                CP16(dstB + ((chalf * 4 + j) ^ cxor) * 16, srcB + j * 16);
        }
        CPCOMMIT();
    };
    auto compute = [&](int stage) {
        uint32_t Ab = sb + stage * STAGE_SZ + aRowOff;
        uint32_t Bb = sb + stage * STAGE_SZ + 16384 + bRowOff;
#pragma unroll
        for (int s = 0; s < 2; s++) {
            uint32_t bh[8], bl[8];
#pragma unroll
            for (int nb = 0; nb < 2; nb++) {
                ldsm4(Bb + nb * 2048 + (((s * 2 + bKsel)) ^ xr) * 16, bh + 4 * nb);
                ldsm4(Bb + nb * 2048 + ((4 + s * 2 + bKsel) ^ xr) * 16, bl + 4 * nb);
            }
#pragma unroll
            for (int mi = 0; mi < 4; mi++) {
                uint32_t ah[4], al[4];
                ldsm4(Ab + mi * 2048 + (((s * 2 + aKsel)) ^ xr) * 16, ah);
                ldsm4(Ab + mi * 2048 + ((4 + s * 2 + aKsel) ^ xr) * 16, al);
#pragma unroll
                for (int nj = 0; nj < 4; nj++) {
                    float* cc = acc[mi][nj];
                    mma_bf16(cc, ah, bh[2 * nj], bh[2 * nj + 1]);
                    mma_bf16(cc, ah, bl[2 * nj], bl[2 * nj + 1]);
                    mma_bf16(cc, al, bh[2 * nj], bh[2 * nj + 1]);
                }
            }
        }
    };

    const int rloc = warp_m * 64 + (lane >> 2);
    const int nl0 = warp_n * 32 + (lane & 3) * 2;

    // ---- prologue: streams 0 and 1 ----
    prefetch(0);
    prefetch(1);
    if (MODE == 0) {
        loadA_regs(0);
        storeA_regs(0);
        if (total > 1) loadA_regs(1);
    }

    // ---- continuous main loop over all (tile, chunk) streams ----
    for (int s = 0; s < total; s++) {
        const int stg = s % NSTAGE;
        CPWAIT1();
        __syncthreads();
        prefetch(s + 2);
        compute(stg);
        if (MODE == 0) {
            if (s + 1 < total) {
                storeA_regs((s + 1) % NSTAGE);
                if (s + 2 < total) loadA_regs(s + 2);
            }
        }

        // ---- tile boundary: epilogue + acc reset ----
        if ((s % NC) == NC - 1) {
            const int t = bid + (s / NC) * GRID;
            const size_t mBase = (size_t)(t >> 1) * 128;
            const int nBase = (t & 1) * 128;
            if (MODE == 0) {
#pragma unroll
                for (int mi = 0; mi < 4; mi++)
#pragma unroll
                    for (int nj = 0; nj < 4; nj++) {
                        int nl = nl0 + nj * 8;
                        float b0v = biasS[nBase + nl], b1v = biasS[nBase + nl + 1];
                        float v00 = fmaxf(acc[mi][nj][0] + b0v, 0.f);
                        float v01 = fmaxf(acc[mi][nj][1] + b1v, 0.f);
                        float v10 = fmaxf(acc[mi][nj][2] + b0v, 0.f);
                        float v11 = fmaxf(acc[mi][nj][3] + b1v, 0.f);
                        int gn = nBase + nl;
                        int cpk = gn >> 5, slot = gn & 31;
                        size_t r0 = mBase + rloc + mi * 16;
                        size_t o0 = ((size_t)cpk * M_ROWS + r0) * 64 + slot;
                        size_t o1 = o0 + 8 * 64;
                        uint32_t h, l;
                        split2(v00, v01, h, l);
                        *(uint32_t*)(outp + o0) = h;
                        *(uint32_t*)(outp + o0 + 32) = l;
                        split2(v10, v11, h, l);
                        *(uint32_t*)(outp + o1) = h;
                        *(uint32_t*)(outp + o1 + 32) = l;
                        acc[mi][nj][0] = 0.f; acc[mi][nj][1] = 0.f;
                        acc[mi][nj][2] = 0.f; acc[mi][nj][3] = 0.f;
                    }
            } else {
                float up[16];
#pragma unroll
                for (int i = 0; i < 16; i++) up[i] = 0.f;
#pragma unroll
                for (int mi = 0; mi < 4; mi++)
#pragma unroll
                    for (int nj = 0; nj < 4; nj++) {
                        int nl = nl0 + nj * 8;
                        float b0v = biasS[nBase + nl], b1v = biasS[nBase + nl + 1];
                        float w00 = W2s[2 * (nBase + nl)],     w01 = W2s[2 * (nBase + nl) + 1];
                        float w10 = W2s[2 * (nBase + nl) + 2], w11 = W2s[2 * (nBase + nl) + 3];
                        float v00 = fmaxf(acc[mi][nj][0] + b0v, 0.f);
                        float v01 = fmaxf(acc[mi][nj][1] + b1v, 0.f);
                        float v10 = fmaxf(acc[mi][nj][2] + b0v, 0.f);
                        float v11 = fmaxf(acc[mi][nj][3] + b1v, 0.f);
                        up[mi * 4 + 0] += v00 * w00 + v01 * w10;
                        up[mi * 4 + 1] += v00 * w01 + v01 * w11;
                        up[mi * 4 + 2] += v10 * w00 + v11 * w10;
                        up[mi * 4 + 3] += v10 * w01 + v11 * w11;
                        acc[mi][nj][0] = 0.f; acc[mi][nj][1] = 0.f;
                        acc[mi][nj][2] = 0.f; acc[mi][nj][3] = 0.f;
                    }
#pragma unroll
                for (int k = 1; k <= 2; k <<= 1)
#pragma unroll
                    for (int i = 0; i < 16; i++)
                        up[i] += __shfl_xor_sync(0xffffffffu, up[i], k);
                if ((lane & 3) == 0) {
#pragma unroll
                    for (int mi = 0; mi < 4; mi++) {
                        size_t r0 = mBase + rloc + mi * 16;
                        size_t r1 = r0 + 8;
                        atomicAdd(&un[r0 * 2 + 0], up[mi * 4 + 0]);
                        atomicAdd(&un[r0 * 2 + 1], up[mi * 4 + 1]);
                        atomicAdd(&un[r1 * 2 + 0], up[mi * 4 + 2]);
                        atomicAdd(&un[r1 * 2 + 1], up[mi * 4 + 3]);
                    }
                }
            }
        }
    }
}

// -------- binary MLP + pairwise config sums ----------------------------------
__global__ __launch_bounds__(128) void binary_kernel(
    const float* __restrict__ ctx, const float* __restrict__ R0,
    const float* __restrict__ r0, const float* __restrict__ R1,
    const float* __restrict__ r1, float* __restrict__ pairsum)
{
    __shared__ float cd[NPAIR][5];
    __shared__ float R0s[5][RHv];
    __shared__ float r0s[RHv];
    __shared__ float R1s[RHv][3];
    __shared__ float r1s[3];
    __shared__ float h2s[NPAIR][RHv];
    __shared__ float bp4s[NPAIR][4];

    int b = blockIdx.x, t = threadIdx.x;
    for (int i = t; i < NPAIR * 5; i += 128) cd[i / 5][i % 5] = ctx[b * NPAIR * 5 + i];
    for (int i = t; i < 5 * RHv; i += 128) R0s[i / RHv][i % RHv] = R0[i];
    if (t < RHv) r0s[t] = r0[t];
    for (int i = t; i < RHv * 3; i += 128) R1s[i / 3][i % 3] = R1[i];
    if (t < 3) r1s[t] = r1[t];
    __syncthreads();

    for (int idx = t; idx < NPAIR * RHv; idx += 128) {
        int p = idx / RHv, u = idx % RHv;
        float v = r0s[u];
#pragma unroll
        for (int x = 0; x < 5; x++) v += cd[p][x] * R0s[x][u];
        h2s[p][u] = fmaxf(v, 0.f);
    }
    __syncthreads();

    if (t < NPAIR * 3) {
        int p = t / 3, y = t % 3;
        float v = r1s[y];
#pragma unroll
        for (int u = 0; u < RHv; u++) v += h2s[p][u] * R1s[u][y];
        if (y == 0) bp4s[p][0] = v;
        else if (y == 1) { bp4s[p][1] = v; bp4s[p][2] = v; }
        else bp4s[p][3] = v;
    }
    __syncthreads();

    int s = t;
    float accv = 0.f;
    int p = 0;
#pragma unroll
    for (int i = 0; i < NE; i++)
#pragma unroll
        for (int j = i + 1; j < NE; j++) {
            int bi = (s >> (6 - i)) & 1;
            int bj = (s >> (6 - j)) & 1;
            accv += bp4s[p][bi * 2 + bj];
            p++;
        }
    pairsum[(size_t)b * NCFG + s] = accv;
}

// ---------------- joint + lse + marginals: one warp per (n,b) -----------------
__global__ __launch_bounds__(256) void joint_kernel(
    const float* __restrict__ un, const float* __restrict__ ps,
    const float* __restrict__ b2v, float* __restrict__ out_marg,
    float* __restrict__ out_joint)
{
    int w = blockIdx.x * 8 + (threadIdx.x >> 5);
    int lane = threadIdx.x & 31;
    int b = w & (BSZv - 1), n = w >> 9;
    size_t nb = (size_t)n * BSZv + b;

    float val = 0.f;
    if (lane < 14) val = un[nb * 14 + lane] + b2v[lane & 1];
    float u[14];
#pragma unroll
    for (int i = 0; i < 14; i++) u[i] = __shfl_sync(0xffffffffu, val, i);

    float j[4], e[4];
    float mx = -1e30f;
#pragma unroll
    for (int q = 0; q < 4; q++) {
        int s = q * 32 + lane;
        float t = ps[(size_t)b * NCFG + s];
#pragma unroll
        for (int i = 0; i < NE; i++) t += u[i * 2 + ((s >> (6 - i)) & 1)];
        j[q] = t;
        mx = fmaxf(mx, t);
    }
#pragma unroll
    for (int o = 16; o; o >>= 1) mx = fmaxf(mx, __shfl_xor_sync(0xffffffffu, mx, o));

    float p1[NE], p0[NE];
#pragma unroll
    for (int i = 0; i < NE; i++) { p1[i] = 0.f; p0[i] = 0.f; }
#pragma unroll
    for (int q = 0; q < 4; q++) {
        int s = q * 32 + lane;
        e[q] = __expf(j[q] - mx);
#pragma unroll
        for (int i = 0; i < NE; i++) {
            if ((s >> (6 - i)) & 1) p1[i] += e[q];
            else p0[i] += e[q];
        }
    }
#pragma unroll
    for (int o = 16; o; o >>= 1)
#pragma unroll
        for (int i = 0; i < NE; i++) {
            p1[i] += __shfl_xor_sync(0xffffffffu, p1[i], o);
            p0[i] += __shfl_xor_sync(0xffffffffu, p0[i], o);
        }

    float lt = __logf(p1[0] + p0[0]);
#pragma unroll
    for (int q = 0; q < 4; q++)
        out_joint[nb * NCFG + q * 32 + lane] = j[q] - mx - lt;
    if (lane < NE)
        out_marg[nb * NE + lane] = __logf(p1[lane]) - __logf(p0[lane]);
}

// ---------------- launch -------------------------------------------------------
extern "C" void kernel_launch(void* const* d_in, const int* in_sizes, int n_in,
                              void* d_out, int out_size)
{
    const float* input = (const float*)d_in[0];
    const float* ctx   = (const float*)d_in[1];
    const float* W0 = (const float*)d_in[4];
    const float* b0 = (const float*)d_in[5];
    const float* W1 = (const float*)d_in[6];
    const float* b1 = (const float*)d_in[7];
    const float* W2 = (const float*)d_in[8];
    const float* b2 = (const float*)d_in[9];
    const float* R0 = (const float*)d_in[10];
    const float* r0 = (const float*)d_in[11];
    const float* R1 = (const float*)d_in[12];
    const float* r1 = (const float*)d_in[13];

    float* out = (float*)d_out;
    float* out_marg = out;
    float* out_joint = out + (size_t)M_ROWS;

    __nv_bfloat16 *w0p, *w1p, *h1p;
    float *un, *psum;
    cudaGetSymbolAddress((void**)&w0p, g_w0p);
    cudaGetSymbolAddress((void**)&w1p, g_w1p);
    cudaGetSymbolAddress((void**)&h1p, g_h1p);
    cudaGetSymbolAddress((void**)&un, g_un);
    cudaGetSymbolAddress((void**)&psum, g_pairsum);

    cudaFuncSetAttribute(gemm_tc<DIN, 0>, cudaFuncAttributeMaxDynamicSharedMemorySize, SMEM_SZ);
    cudaFuncSetAttribute(gemm_tc<DHv, 1>, cudaFuncAttributeMaxDynamicSharedMemorySize, SMEM_SZ);

    pack_weights<<<DIN, 256>>>(W0, w0p, DIN);
    pack_weights<<<DHv, 256>>>(W1, w1p, DHv);
    cudaMemsetAsync(un, 0, (size_t)M_ROWS * 2 * sizeof(float));

    gemm_tc<DIN, 0><<<PGRID, 256, SMEM_SZ>>>(
        input, nullptr, w0p, b0, nullptr, h1p, nullptr);
    gemm_tc<DHv, 1><<<PGRID, 256, SMEM_SZ>>>(
        nullptr, h1p, w1p, b1, W2, nullptr, un);
    binary_kernel<<<BSZv, 128>>>(ctx, R0, r0, R1, r1, psum);
    joint_kernel<<<(NN * BSZv) / 8, 256>>>(un, psum, b2, out_marg, out_joint);
}

// round 8
// speedup vs baseline: 1.3890x; 1.3688x over previous
#include <cuda_runtime.h>
#include <cuda_fp16.h>
#include <cstdint>
#include <math.h>

#define NN    32
#define BSZv  512
#define NE    7
#define DIN   512
#define DHv   256
#define RHv   64
#define NPAIR 21
#define M_ROWS (NN * BSZv * NE)   // 114688
#define NCFG  128
#define NTILES 1792
#define PGRID  304

// ---------------- scratch (device globals; no allocation allowed) ------------
// B packed: [k-chunk][n=256][64 fp16 = hi(32 k) | lo(32 k)]  (128B per row)
__device__ __align__(128) __half g_w0p[(size_t)(DIN / 32) * DHv * 64];
__device__ __align__(128) __half g_w1p[(size_t)(DHv / 32) * DHv * 64];
// A packed (h1): [k-chunk][row][32 fp16]  (64B per row, single precision level)
__device__ __align__(128) __half g_h1p[(size_t)(DHv / 32) * M_ROWS * 32];
__device__ float g_un[(size_t)M_ROWS * 2];
__device__ float g_pairsum[(size_t)BSZv * NCFG];

// ---------------- PTX helpers ------------------------------------------------
__device__ __forceinline__ uint32_t smem_u32(const void* p) {
    uint32_t a;
    asm("{ .reg .u64 t; cvta.to.shared.u64 t, %1; cvt.u32.u64 %0, t; }" : "=r"(a) : "l"(p));
    return a;
}
__device__ __forceinline__ void ldsm4(uint32_t a, uint32_t* r) {
    asm volatile("ldmatrix.sync.aligned.m8n8.x4.shared.b16 {%0,%1,%2,%3}, [%4];"
                 : "=r"(r[0]), "=r"(r[1]), "=r"(r[2]), "=r"(r[3]) : "r"(a));
}
__device__ __forceinline__ void mma_f16(float* c, const uint32_t* a, uint32_t b0, uint32_t b1) {
    asm volatile("mma.sync.aligned.m16n8k16.row.col.f32.f16.f16.f32 "
                 "{%0,%1,%2,%3}, {%4,%5,%6,%7}, {%8,%9}, {%0,%1,%2,%3};"
                 : "+f"(c[0]), "+f"(c[1]), "+f"(c[2]), "+f"(c[3])
                 : "r"(a[0]), "r"(a[1]), "r"(a[2]), "r"(a[3]), "r"(b0), "r"(b1));
}
#define CP16(dst, src) asm volatile("cp.async.cg.shared.global [%0], [%1], 16;" :: "r"(dst), "l"(src))
#define CPCOMMIT()     asm volatile("cp.async.commit_group;" ::: "memory")
#define CPWAIT1()      asm volatile("cp.async.wait_group 1;" ::: "memory")
#define STS128(a, v0, v1, v2, v3) \
    asm volatile("st.shared.v4.b32 [%0], {%1,%2,%3,%4};" :: "r"(a), "r"(v0), "r"(v1), "r"(v2), "r"(v3))

__device__ __forceinline__ uint32_t pack2h(__half a, __half b) {
    __half2 t = __halves2half2(a, b);
    return *reinterpret_cast<uint32_t*>(&t);
}

// ---------------- weight packing: fp16 hi/lo ----------------------------------
__global__ __launch_bounds__(256) void pack_weights(
    const float* __restrict__ W, __half* __restrict__ dst, int K)
{
    int idx = blockIdx.x * 256 + threadIdx.x;
    if (idx >= K * 256) return;
    int k = idx >> 8, n = idx & 255;
    float v = W[idx];
    __half h = __float2half_rn(v);
    __half l = __float2half_rn(v - __half2float(h));
    size_t o = ((size_t)(k >> 5) * 256 + n) * 64 + (k & 31);
    dst[o] = h;
    dst[o + 32] = l;
}

// ---------------- GEMM (mma.sync fp16x2, persistent) ---------------------------
// A smem: 128 rows x 128B; chunk uses 4 logical 16B groups g=0..3 at phys (2g)^ (r&7)
// B smem: unchanged 8-group layout (hi 0-3 | lo 4-7), phys g ^ (r&7)
#define NSTAGE   3
#define STAGE_SZ 32768
#define SM_BIAS  (NSTAGE * STAGE_SZ)
#define SM_W2    (SM_BIAS + 1024)
#define SMEM_SZ  (SM_W2 + 2048)

template <int KDIM, int MODE>
__global__ __launch_bounds__(256, 2) void gemm_tc(
    const float* __restrict__ Af, const __half* __restrict__ Ap,
    const __half* __restrict__ Wp, const float* __restrict__ bias,
    const float* __restrict__ W2, __half* __restrict__ outp,
    float* __restrict__ un)
{
    extern __shared__ char smem[];
    constexpr int NC = KDIM / 32;
    const int tid = threadIdx.x;
    const int lane = tid & 31;
    const int wid = tid >> 5;
    const int warp_m = wid >> 2, warp_n = wid & 3;
    const int bid = blockIdx.x;
    const int GRID = gridDim.x;

    const uint32_t sb = smem_u32(smem);
    float* biasS = (float*)(smem + SM_BIAS);
    float* W2s = (float*)(smem + SM_W2);
    biasS[tid] = bias[tid];
    if (MODE == 1) { W2s[tid] = W2[tid]; W2s[tid + 256] = W2[tid + 256]; }

    const int crow = tid >> 1;
    const int chalf = tid & 1;
    const int cxor = crow & 7;

    const uint32_t aRowOff = (uint32_t)(warp_m * 64 + (lane & 15)) * 128;
    const uint32_t aKsel = (uint32_t)(lane >> 4);
    const uint32_t bRowOff = (uint32_t)(warp_n * 32 + ((lane >> 4) << 3) + (lane & 7)) * 128;
    const uint32_t bKsel = (uint32_t)((lane >> 3) & 1);
    const uint32_t xr = (uint32_t)(lane & 7);

    const int myTiles = (NTILES - bid + GRID - 1) / GRID;
    const int total = myTiles * NC;

    float acc[4][4][4];
#pragma unroll
    for (int a = 0; a < 4; a++)
#pragma unroll
        for (int b = 0; b < 4; b++)
#pragma unroll
            for (int q = 0; q < 4; q++) acc[a][b][q] = 0.f;

    float rA[16];   // MODE0 staging

    auto loadA_regs = [&](int s) {            // MODE0 only
        int i = s / NC, c = s % NC;
        int t = bid + i * GRID;
        size_t mB = (size_t)(t >> 1) * 128;
        const float* p = Af + (mB + crow) * KDIM + c * 32 + chalf * 16;
        *(float4*)(rA)      = *(const float4*)(p);
        *(float4*)(rA + 4)  = *(const float4*)(p + 4);
        *(float4*)(rA + 8)  = *(const float4*)(p + 8);
        *(float4*)(rA + 12) = *(const float4*)(p + 12);
    };
    // 16 fp32 -> 16 fp16 -> 2 x 16B groups, logical g = 2*chalf + h
    auto storeA_regs = [&](int stg) {
        uint32_t dst = sb + stg * STAGE_SZ + crow * 128;
        uint32_t hh[8];
#pragma unroll
        for (int q = 0; q < 8; q++)
            hh[q] = pack2h(__float2half_rn(rA[2 * q]), __float2half_rn(rA[2 * q + 1]));
        STS128(dst + ((2 * (2 * chalf + 0)) ^ cxor) * 16, hh[0], hh[1], hh[2], hh[3]);
        STS128(dst + ((2 * (2 * chalf + 1)) ^ cxor) * 16, hh[4], hh[5], hh[6], hh[7]);
    };
    auto prefetch = [&](int s) {
        if (s < total) {
            int i = s / NC, c = s % NC;
            int t = bid + i * GRID;
            int stage = s % NSTAGE;
            int nB = (t & 1) * 128;
            if (MODE == 1) {
                size_t mB = (size_t)(t >> 1) * 128;
                // A row = 32 fp16 = 64B; thread half = 32B = 2 logical groups
                const char* srcA = (const char*)(Ap + ((size_t)c * M_ROWS + mB + crow) * 32 + chalf * 16);
                uint32_t dstA = sb + stage * STAGE_SZ + crow * 128;
#pragma unroll
                for (int j = 0; j < 2; j++)
                    CP16(dstA + ((2 * (2 * chalf + j)) ^ cxor) * 16, srcA + j * 16);
            }
            const char* srcB = (const char*)(Wp + ((size_t)c * 256 + nB + crow) * 64 + chalf * 32);
            uint32_t dstB = sb + stage * STAGE_SZ + 16384 + crow * 128;
#pragma unroll
            for (int j = 0; j < 4; j++)
                CP16(dstB + ((chalf * 4 + j) ^ cxor) * 16, srcB + j * 16);
        }
        CPCOMMIT();
    };
    auto compute = [&](int stage) {
        uint32_t Ab = sb + stage * STAGE_SZ + aRowOff;
        uint32_t Bb = sb + stage * STAGE_SZ + 16384 + bRowOff;
#pragma unroll
        for (int s = 0; s < 2; s++) {
            uint32_t bh[8], bl[8];
#pragma unroll
            for (int nb = 0; nb < 2; nb++) {
                ldsm4(Bb + nb * 2048 + (((s * 2 + bKsel)) ^ xr) * 16, bh + 4 * nb);
                ldsm4(Bb + nb * 2048 + ((4 + s * 2 + bKsel) ^ xr) * 16, bl + 4 * nb);
            }
#pragma unroll
            for (int mi = 0; mi < 4; mi++) {
                uint32_t ah[4];
                ldsm4(Ab + mi * 2048 + ((2 * (s * 2 + aKsel)) ^ xr) * 16, ah);
#pragma unroll
                for (int nj = 0; nj < 4; nj++) {
                    float* cc = acc[mi][nj];
                    mma_f16(cc, ah, bh[2 * nj], bh[2 * nj + 1]);
                    mma_f16(cc, ah, bl[2 * nj], bl[2 * nj + 1]);
                }
            }
        }
    };

    const int rloc = warp_m * 64 + (lane >> 2);
    const int nl0 = warp_n * 32 + (lane & 3) * 2;

    // ---- prologue ----
    prefetch(0);
    prefetch(1);
    if (MODE == 0) {
        loadA_regs(0);
        storeA_regs(0);
        if (total > 1) loadA_regs(1);
    }

    // ---- continuous main loop ----
    for (int s = 0; s < total; s++) {
        const int stg = s % NSTAGE;
        CPWAIT1();
        __syncthreads();
        prefetch(s + 2);
        compute(stg);
        if (MODE == 0) {
            if (s + 1 < total) {
                storeA_regs((s + 1) % NSTAGE);
                if (s + 2 < total) loadA_regs(s + 2);
            }
        }

        if ((s % NC) == NC - 1) {
            const int t = bid + (s / NC) * GRID;
            const size_t mBase = (size_t)(t >> 1) * 128;
            const int nBase = (t & 1) * 128;
            if (MODE == 0) {
#pragma unroll
                for (int mi = 0; mi < 4; mi++)
#pragma unroll
                    for (int nj = 0; nj < 4; nj++) {
                        int nl = nl0 + nj * 8;
                        float b0v = biasS[nBase + nl], b1v = biasS[nBase + nl + 1];
                        float v00 = fmaxf(acc[mi][nj][0] + b0v, 0.f);
                        float v01 = fmaxf(acc[mi][nj][1] + b1v, 0.f);
                        float v10 = fmaxf(acc[mi][nj][2] + b0v, 0.f);
                        float v11 = fmaxf(acc[mi][nj][3] + b1v, 0.f);
                        int gn = nBase + nl;
                        int cpk = gn >> 5, slot = gn & 31;
                        size_t r0 = mBase + rloc + mi * 16;
                        size_t o0 = ((size_t)cpk * M_ROWS + r0) * 32 + slot;
                        size_t o1 = o0 + 8 * 32;
                        *(uint32_t*)(outp + o0) =
                            pack2h(__float2half_rn(v00), __float2half_rn(v01));
                        *(uint32_t*)(outp + o1) =
                            pack2h(__float2half_rn(v10), __float2half_rn(v11));
                        acc[mi][nj][0] = 0.f; acc[mi][nj][1] = 0.f;
                        acc[mi][nj][2] = 0.f; acc[mi][nj][3] = 0.f;
                    }
            } else {
                float up[16];
#pragma unroll
                for (int i = 0; i < 16; i++) up[i] = 0.f;
#pragma unroll
                for (int mi = 0; mi < 4; mi++)
#pragma unroll
                    for (int nj = 0; nj < 4; nj++) {
                        int nl = nl0 + nj * 8;
                        float b0v = biasS[nBase + nl], b1v = biasS[nBase + nl + 1];
                        float w00 = W2s[2 * (nBase + nl)],     w01 = W2s[2 * (nBase + nl) + 1];
                        float w10 = W2s[2 * (nBase + nl) + 2], w11 = W2s[2 * (nBase + nl) + 3];
                        float v00 = fmaxf(acc[mi][nj][0] + b0v, 0.f);
                        float v01 = fmaxf(acc[mi][nj][1] + b1v, 0.f);
                        float v10 = fmaxf(acc[mi][nj][2] + b0v, 0.f);
                        float v11 = fmaxf(acc[mi][nj][3] + b1v, 0.f);
                        up[mi * 4 + 0] += v00 * w00 + v01 * w10;
                        up[mi * 4 + 1] += v00 * w01 + v01 * w11;
                        up[mi * 4 + 2] += v10 * w00 + v11 * w10;
                        up[mi * 4 + 3] += v10 * w01 + v11 * w11;
                        acc[mi][nj][0] = 0.f; acc[mi][nj][1] = 0.f;
                        acc[mi][nj][2] = 0.f; acc[mi][nj][3] = 0.f;
                    }
#pragma unroll
                for (int k = 1; k <= 2; k <<= 1)
#pragma unroll
                    for (int i = 0; i < 16; i++)
                        up[i] += __shfl_xor_sync(0xffffffffu, up[i], k);
                if ((lane & 3) == 0) {
#pragma unroll
                    for (int mi = 0; mi < 4; mi++) {
                        size_t r0 = mBase + rloc + mi * 16;
                        size_t r1 = r0 + 8;
                        atomicAdd(&un[r0 * 2 + 0], up[mi * 4 + 0]);
                        atomicAdd(&un[r0 * 2 + 1], up[mi * 4 + 1]);
                        atomicAdd(&un[r1 * 2 + 0], up[mi * 4 + 2]);
                        atomicAdd(&un[r1 * 2 + 1], up[mi * 4 + 3]);
                    }
                }
            }
        }
    }
}

// -------- binary MLP + pairwise config sums ----------------------------------
__global__ __launch_bounds__(128) void binary_kernel(
    const float* __restrict__ ctx, const float* __restrict__ R0,
    const float* __restrict__ r0, const float* __restrict__ R1,
    const float* __restrict__ r1, float* __restrict__ pairsum)
{
    __shared__ float cd[NPAIR][5];
    __shared__ float R0s[5][RHv];
    __shared__ float r0s[RHv];
    __shared__ float R1s[RHv][3];
    __shared__ float r1s[3];
    __shared__ float h2s[NPAIR][RHv];
    __shared__ float bp4s[NPAIR][4];

    int b = blockIdx.x, t = threadIdx.x;
    for (int i = t; i < NPAIR * 5; i += 128) cd[i / 5][i % 5] = ctx[b * NPAIR * 5 + i];
    for (int i = t; i < 5 * RHv; i += 128) R0s[i / RHv][i % RHv] = R0[i];
    if (t < RHv) r0s[t] = r0[t];
    for (int i = t; i < RHv * 3; i += 128) R1s[i / 3][i % 3] = R1[i];
    if (t < 3) r1s[t] = r1[t];
    __syncthreads();

    for (int idx = t; idx < NPAIR * RHv; idx += 128) {
        int p = idx / RHv, u = idx % RHv;
        float v = r0s[u];
#pragma unroll
        for (int x = 0; x < 5; x++) v += cd[p][x] * R0s[x][u];
        h2s[p][u] = fmaxf(v, 0.f);
    }
    __syncthreads();

    if (t < NPAIR * 3) {
        int p = t / 3, y = t % 3;
        float v = r1s[y];
#pragma unroll
        for (int u = 0; u < RHv; u++) v += h2s[p][u] * R1s[u][y];
        if (y == 0) bp4s[p][0] = v;
        else if (y == 1) { bp4s[p][1] = v; bp4s[p][2] = v; }
        else bp4s[p][3] = v;
    }
    __syncthreads();

    int s = t;
    float accv = 0.f;
    int p = 0;
#pragma unroll
    for (int i = 0; i < NE; i++)
#pragma unroll
        for (int j = i + 1; j < NE; j++) {
            int bi = (s >> (6 - i)) & 1;
            int bj = (s >> (6 - j)) & 1;
            accv += bp4s[p][bi * 2 + bj];
            p++;
        }
    pairsum[(size_t)b * NCFG + s] = accv;
}

// ---------------- joint + lse + marginals: one warp per (n,b) -----------------
__global__ __launch_bounds__(256) void joint_kernel(
    const float* __restrict__ un, const float* __restrict__ ps,
    const float* __restrict__ b2v, float* __restrict__ out_marg,
    float* __restrict__ out_joint)
{
    int w = blockIdx.x * 8 + (threadIdx.x >> 5);
    int lane = threadIdx.x & 31;
    int b = w & (BSZv - 1), n = w >> 9;
    size_t nb = (size_t)n * BSZv + b;

    float val = 0.f;
    if (lane < 14) val = un[nb * 14 + lane] + b2v[lane & 1];
    float u[14];
#pragma unroll
    for (int i = 0; i < 14; i++) u[i] = __shfl_sync(0xffffffffu, val, i);

    float j[4], e[4];
    float mx = -1e30f;
#pragma unroll
    for (int q = 0; q < 4; q++) {
        int s = q * 32 + lane;
        float t = ps[(size_t)b * NCFG + s];
#pragma unroll
        for (int i = 0; i < NE; i++) t += u[i * 2 + ((s >> (6 - i)) & 1)];
        j[q] = t;
        mx = fmaxf(mx, t);
    }
#pragma unroll
    for (int o = 16; o; o >>= 1) mx = fmaxf(mx, __shfl_xor_sync(0xffffffffu, mx, o));

    float p1[NE], p0[NE];
#pragma unroll
    for (int i = 0; i < NE; i++) { p1[i] = 0.f; p0[i] = 0.f; }
#pragma unroll
    for (int q = 0; q < 4; q++) {
        int s = q * 32 + lane;
        e[q] = __expf(j[q] - mx);
#pragma unroll
        for (int i = 0; i < NE; i++) {
            if ((s >> (6 - i)) & 1) p1[i] += e[q];
            else p0[i] += e[q];
        }
    }
#pragma unroll
    for (int o = 16; o; o >>= 1)
#pragma unroll
        for (int i = 0; i < NE; i++) {
            p1[i] += __shfl_xor_sync(0xffffffffu, p1[i], o);
            p0[i] += __shfl_xor_sync(0xffffffffu, p0[i], o);
        }

    float lt = __logf(p1[0] + p0[0]);
#pragma unroll
    for (int q = 0; q < 4; q++)
        out_joint[nb * NCFG + q * 32 + lane] = j[q] - mx - lt;
    if (lane < NE)
        out_marg[nb * NE + lane] = __logf(p1[lane]) - __logf(p0[lane]);
}

// ---------------- launch -------------------------------------------------------
extern "C" void kernel_launch(void* const* d_in, const int* in_sizes, int n_in,
                              void* d_out, int out_size)
{
    const float* input = (const float*)d_in[0];
    const float* ctx   = (const float*)d_in[1];
    const float* W0 = (const float*)d_in[4];
    const float* b0 = (const float*)d_in[5];
    const float* W1 = (const float*)d_in[6];
    const float* b1 = (const float*)d_in[7];
    const float* W2 = (const float*)d_in[8];
    const float* b2 = (const float*)d_in[9];
    const float* R0 = (const float*)d_in[10];
    const float* r0 = (const float*)d_in[11];
    const float* R1 = (const float*)d_in[12];
    const float* r1 = (const float*)d_in[13];

    float* out = (float*)d_out;
    float* out_marg = out;
    float* out_joint = out + (size_t)M_ROWS;

    __half *w0p, *w1p, *h1p;
    float *un, *psum;
    cudaGetSymbolAddress((void**)&w0p, g_w0p);
    cudaGetSymbolAddress((void**)&w1p, g_w1p);
    cudaGetSymbolAddress((void**)&h1p, g_h1p);
    cudaGetSymbolAddress((void**)&un, g_un);
    cudaGetSymbolAddress((void**)&psum, g_pairsum);

    cudaFuncSetAttribute(gemm_tc<DIN, 0>, cudaFuncAttributeMaxDynamicSharedMemorySize, SMEM_SZ);
    cudaFuncSetAttribute(gemm_tc<DHv, 1>, cudaFuncAttributeMaxDynamicSharedMemorySize, SMEM_SZ);

    pack_weights<<<DIN, 256>>>(W0, w0p, DIN);
    pack_weights<<<DHv, 256>>>(W1, w1p, DHv);
    cudaMemsetAsync(un, 0, (size_t)M_ROWS * 2 * sizeof(float));

    gemm_tc<DIN, 0><<<PGRID, 256, SMEM_SZ>>>(
        input, nullptr, w0p, b0, nullptr, h1p, nullptr);
    gemm_tc<DHv, 1><<<PGRID, 256, SMEM_SZ>>>(
        nullptr, h1p, w1p, b1, W2, nullptr, un);
    binary_kernel<<<BSZv, 128>>>(ctx, R0, r0, R1, r1, psum);
    joint_kernel<<<(NN * BSZv) / 8, 256>>>(un, psum, b2, out_marg, out_joint);
}

// round 9
// speedup vs baseline: 1.6557x; 1.1920x over previous
#include <cuda_runtime.h>
#include <cuda_fp16.h>
#include <cstdint>
#include <math.h>

#define NN    32
#define BSZv  512
#define NE    7
#define DIN   512
#define DHv   256
#define RHv   64
#define NPAIR 21
#define M_ROWS (NN * BSZv * NE)   // 114688
#define NCFG  128
#define NTILES 1792
#define PGRID  304

// ---------------- scratch (device globals; no allocation allowed) ------------
// B packed: [k-chunk][n=256][32 fp16]  (64B per row, single precision)
__device__ __align__(128) __half g_w0p[(size_t)(DIN / 32) * DHv * 32];
__device__ __align__(128) __half g_w1p[(size_t)(DHv / 32) * DHv * 32];
// A packed (h1): [k-chunk][row][32 fp16]
__device__ __align__(128) __half g_h1p[(size_t)(DHv / 32) * M_ROWS * 32];
__device__ float g_un[(size_t)M_ROWS * 2];
__device__ float g_pairsum[(size_t)BSZv * NCFG];

// ---------------- PTX helpers ------------------------------------------------
__device__ __forceinline__ uint32_t smem_u32(const void* p) {
    uint32_t a;
    asm("{ .reg .u64 t; cvta.to.shared.u64 t, %1; cvt.u32.u64 %0, t; }" : "=r"(a) : "l"(p));
    return a;
}
__device__ __forceinline__ void ldsm4(uint32_t a, uint32_t* r) {
    asm volatile("ldmatrix.sync.aligned.m8n8.x4.shared.b16 {%0,%1,%2,%3}, [%4];"
                 : "=r"(r[0]), "=r"(r[1]), "=r"(r[2]), "=r"(r[3]) : "r"(a));
}
__device__ __forceinline__ void mma_f16(float* c, const uint32_t* a, uint32_t b0, uint32_t b1) {
    asm volatile("mma.sync.aligned.m16n8k16.row.col.f32.f16.f16.f32 "
                 "{%0,%1,%2,%3}, {%4,%5,%6,%7}, {%8,%9}, {%0,%1,%2,%3};"
                 : "+f"(c[0]), "+f"(c[1]), "+f"(c[2]), "+f"(c[3])
                 : "r"(a[0]), "r"(a[1]), "r"(a[2]), "r"(a[3]), "r"(b0), "r"(b1));
}
#define CP16(dst, src) asm volatile("cp.async.cg.shared.global [%0], [%1], 16;" :: "r"(dst), "l"(src))
#define CPCOMMIT()     asm volatile("cp.async.commit_group;" ::: "memory")
#define CPWAIT1()      asm volatile("cp.async.wait_group 1;" ::: "memory")
#define STS128(a, v0, v1, v2, v3) \
    asm volatile("st.shared.v4.b32 [%0], {%1,%2,%3,%4};" :: "r"(a), "r"(v0), "r"(v1), "r"(v2), "r"(v3))

__device__ __forceinline__ uint32_t pack2h(__half a, __half b) {
    __half2 t = __halves2half2(a, b);
    return *reinterpret_cast<uint32_t*>(&t);
}

// ---------------- weight packing: single fp16 ----------------------------------
__global__ __launch_bounds__(256) void pack_weights(
    const float* __restrict__ W, __half* __restrict__ dst, int K)
{
    int idx = blockIdx.x * 256 + threadIdx.x;
    if (idx >= K * 256) return;
    int k = idx >> 8, n = idx & 255;
    size_t o = ((size_t)(k >> 5) * 256 + n) * 32 + (k & 31);
    dst[o] = __float2half_rn(W[idx]);
}

// ---------------- GEMM (mma.sync fp16 single-term, persistent) -----------------
// A/B smem: 128 rows x 128B region; 4 logical 16B groups at phys (2g)^(r&7)
#define NSTAGE   3
#define STAGE_SZ 32768
#define SM_BIAS  (NSTAGE * STAGE_SZ)
#define SM_W2    (SM_BIAS + 1024)
#define SMEM_SZ  (SM_W2 + 2048)

template <int KDIM, int MODE>
__global__ __launch_bounds__(256, 2) void gemm_tc(
    const float* __restrict__ Af, const __half* __restrict__ Ap,
    const __half* __restrict__ Wp, const float* __restrict__ bias,
    const float* __restrict__ W2, __half* __restrict__ outp,
    float* __restrict__ un)
{
    extern __shared__ char smem[];
    constexpr int NC = KDIM / 32;
    const int tid = threadIdx.x;
    const int lane = tid & 31;
    const int wid = tid >> 5;
    const int warp_m = wid >> 2, warp_n = wid & 3;
    const int bid = blockIdx.x;
    const int GRID = gridDim.x;

    const uint32_t sb = smem_u32(smem);
    float* biasS = (float*)(smem + SM_BIAS);
    float* W2s = (float*)(smem + SM_W2);
    biasS[tid] = bias[tid];
    if (MODE == 1) { W2s[tid] = W2[tid]; W2s[tid + 256] = W2[tid + 256]; }

    const int crow = tid >> 1;
    const int chalf = tid & 1;
    const int cxor = crow & 7;

    const uint32_t aRowOff = (uint32_t)(warp_m * 64 + (lane & 15)) * 128;
    const uint32_t aKsel = (uint32_t)(lane >> 4);
    const uint32_t bRowOff = (uint32_t)(warp_n * 32 + ((lane >> 4) << 3) + (lane & 7)) * 128;
    const uint32_t bKsel = (uint32_t)((lane >> 3) & 1);
    const uint32_t xr = (uint32_t)(lane & 7);

    const int myTiles = (NTILES - bid + GRID - 1) / GRID;
    const int total = myTiles * NC;

    float acc[4][4][4];
#pragma unroll
    for (int a = 0; a < 4; a++)
#pragma unroll
        for (int b = 0; b < 4; b++)
#pragma unroll
            for (int q = 0; q < 4; q++) acc[a][b][q] = 0.f;

    float rA[16];   // MODE0 staging

    auto loadA_regs = [&](int s) {            // MODE0 only
        int i = s / NC, c = s % NC;
        int t = bid + i * GRID;
        size_t mB = (size_t)(t >> 1) * 128;
        const float* p = Af + (mB + crow) * KDIM + c * 32 + chalf * 16;
        *(float4*)(rA)      = *(const float4*)(p);
        *(float4*)(rA + 4)  = *(const float4*)(p + 4);
        *(float4*)(rA + 8)  = *(const float4*)(p + 8);
        *(float4*)(rA + 12) = *(const float4*)(p + 12);
    };
    auto storeA_regs = [&](int stg) {
        uint32_t dst = sb + stg * STAGE_SZ + crow * 128;
        uint32_t hh[8];
#pragma unroll
        for (int q = 0; q < 8; q++)
            hh[q] = pack2h(__float2half_rn(rA[2 * q]), __float2half_rn(rA[2 * q + 1]));
        STS128(dst + ((2 * (2 * chalf + 0)) ^ cxor) * 16, hh[0], hh[1], hh[2], hh[3]);
        STS128(dst + ((2 * (2 * chalf + 1)) ^ cxor) * 16, hh[4], hh[5], hh[6], hh[7]);
    };
    auto prefetch = [&](int s) {
        if (s < total) {
            int i = s / NC, c = s % NC;
            int t = bid + i * GRID;
            int stage = s % NSTAGE;
            int nB = (t & 1) * 128;
            if (MODE == 1) {
                size_t mB = (size_t)(t >> 1) * 128;
                const char* srcA = (const char*)(Ap + ((size_t)c * M_ROWS + mB + crow) * 32 + chalf * 16);
                uint32_t dstA = sb + stage * STAGE_SZ + crow * 128;
#pragma unroll
                for (int j = 0; j < 2; j++)
                    CP16(dstA + ((2 * (2 * chalf + j)) ^ cxor) * 16, srcA + j * 16);
            }
            const char* srcB = (const char*)(Wp + ((size_t)c * 256 + nB + crow) * 32 + chalf * 16);
            uint32_t dstB = sb + stage * STAGE_SZ + 16384 + crow * 128;
#pragma unroll
            for (int j = 0; j < 2; j++)
                CP16(dstB + ((2 * (2 * chalf + j)) ^ cxor) * 16, srcB + j * 16);
        }
        CPCOMMIT();
    };
    auto compute = [&](int stage) {
        uint32_t Ab = sb + stage * STAGE_SZ + aRowOff;
        uint32_t Bb = sb + stage * STAGE_SZ + 16384 + bRowOff;
#pragma unroll
        for (int s = 0; s < 2; s++) {
            uint32_t bh[8];
#pragma unroll
            for (int nb = 0; nb < 2; nb++)
                ldsm4(Bb + nb * 2048 + ((2 * (s * 2 + bKsel)) ^ xr) * 16, bh + 4 * nb);
#pragma unroll
            for (int mi = 0; mi < 4; mi++) {
                uint32_t ah[4];
                ldsm4(Ab + mi * 2048 + ((2 * (s * 2 + aKsel)) ^ xr) * 16, ah);
#pragma unroll
                for (int nj = 0; nj < 4; nj++)
                    mma_f16(acc[mi][nj], ah, bh[2 * nj], bh[2 * nj + 1]);
            }
        }
    };

    const int rloc = warp_m * 64 + (lane >> 2);
    const int nl0 = warp_n * 32 + (lane & 3) * 2;

    // ---- prologue ----
    prefetch(0);
    prefetch(1);
    if (MODE == 0) {
        loadA_regs(0);
        storeA_regs(0);
        if (total > 1) loadA_regs(1);
    }

    // ---- continuous main loop ----
    for (int s = 0; s < total; s++) {
        const int stg = s % NSTAGE;
        CPWAIT1();
        __syncthreads();
        prefetch(s + 2);
        compute(stg);
        if (MODE == 0) {
            if (s + 1 < total) {
                storeA_regs((s + 1) % NSTAGE);
                if (s + 2 < total) loadA_regs(s + 2);
            }
        }

        if ((s % NC) == NC - 1) {
            const int t = bid + (s / NC) * GRID;
            const size_t mBase = (size_t)(t >> 1) * 128;
            const int nBase = (t & 1) * 128;
            if (MODE == 0) {
#pragma unroll
                for (int mi = 0; mi < 4; mi++)
#pragma unroll
                    for (int nj = 0; nj < 4; nj++) {
                        int nl = nl0 + nj * 8;
                        float b0v = biasS[nBase + nl], b1v = biasS[nBase + nl + 1];
                        float v00 = fmaxf(acc[mi][nj][0] + b0v, 0.f);
                        float v01 = fmaxf(acc[mi][nj][1] + b1v, 0.f);
                        float v10 = fmaxf(acc[mi][nj][2] + b0v, 0.f);
                        float v11 = fmaxf(acc[mi][nj][3] + b1v, 0.f);
                        int gn = nBase + nl;
                        int cpk = gn >> 5, slot = gn & 31;
                        size_t r0 = mBase + rloc + mi * 16;
                        size_t o0 = ((size_t)cpk * M_ROWS + r0) * 32 + slot;
                        size_t o1 = o0 + 8 * 32;
                        *(uint32_t*)(outp + o0) =
                            pack2h(__float2half_rn(v00), __float2half_rn(v01));
                        *(uint32_t*)(outp + o1) =
                            pack2h(__float2half_rn(v10), __float2half_rn(v11));
                        acc[mi][nj][0] = 0.f; acc[mi][nj][1] = 0.f;
                        acc[mi][nj][2] = 0.f; acc[mi][nj][3] = 0.f;
                    }
            } else {
                float up[16];
#pragma unroll
                for (int i = 0; i < 16; i++) up[i] = 0.f;
#pragma unroll
                for (int mi = 0; mi < 4; mi++)
#pragma unroll
                    for (int nj = 0; nj < 4; nj++) {
                        int nl = nl0 + nj * 8;
                        float b0v = biasS[nBase + nl], b1v = biasS[nBase + nl + 1];
                        float w00 = W2s[2 * (nBase + nl)],     w01 = W2s[2 * (nBase + nl) + 1];
                        float w10 = W2s[2 * (nBase + nl) + 2], w11 = W2s[2 * (nBase + nl) + 3];
                        float v00 = fmaxf(acc[mi][nj][0] + b0v, 0.f);
                        float v01 = fmaxf(acc[mi][nj][1] + b1v, 0.f);
                        float v10 = fmaxf(acc[mi][nj][2] + b0v, 0.f);
                        float v11 = fmaxf(acc[mi][nj][3] + b1v, 0.f);
                        up[mi * 4 + 0] += v00 * w00 + v01 * w10;
                        up[mi * 4 + 1] += v00 * w01 + v01 * w11;
                        up[mi * 4 + 2] += v10 * w00 + v11 * w10;
                        up[mi * 4 + 3] += v10 * w01 + v11 * w11;
                        acc[mi][nj][0] = 0.f; acc[mi][nj][1] = 0.f;
                        acc[mi][nj][2] = 0.f; acc[mi][nj][3] = 0.f;
                    }
#pragma unroll
                for (int k = 1; k <= 2; k <<= 1)
#pragma unroll
                    for (int i = 0; i < 16; i++)
                        up[i] += __shfl_xor_sync(0xffffffffu, up[i], k);
                if ((lane & 3) == 0) {
#pragma unroll
                    for (int mi = 0; mi < 4; mi++) {
                        size_t r0 = mBase + rloc + mi * 16;
                        size_t r1 = r0 + 8;
                        atomicAdd(&un[r0 * 2 + 0], up[mi * 4 + 0]);
                        atomicAdd(&un[r0 * 2 + 1], up[mi * 4 + 1]);
                        atomicAdd(&un[r1 * 2 + 0], up[mi * 4 + 2]);
                        atomicAdd(&un[r1 * 2 + 1], up[mi * 4 + 3]);
                    }
                }
            }
        }
    }
}

// -------- binary MLP + pairwise config sums ----------------------------------
__global__ __launch_bounds__(128) void binary_kernel(
    const float* __restrict__ ctx, const float* __restrict__ R0,
    const float* __restrict__ r0, const float* __restrict__ R1,
    const float* __restrict__ r1, float* __restrict__ pairsum)
{
    __shared__ float cd[NPAIR][5];
    __shared__ float R0s[5][RHv];
    __shared__ float r0s[RHv];
    __shared__ float R1s[RHv][3];
    __shared__ float r1s[3];
    __shared__ float h2s[NPAIR][RHv];
    __shared__ float bp4s[NPAIR][4];

    int b = blockIdx.x, t = threadIdx.x;
    for (int i = t; i < NPAIR * 5; i += 128) cd[i / 5][i % 5] = ctx[b * NPAIR * 5 + i];
    for (int i = t; i < 5 * RHv; i += 128) R0s[i / RHv][i % RHv] = R0[i];
    if (t < RHv) r0s[t] = r0[t];
    for (int i = t; i < RHv * 3; i += 128) R1s[i / 3][i % 3] = R1[i];
    if (t < 3) r1s[t] = r1[t];
    __syncthreads();

    for (int idx = t; idx < NPAIR * RHv; idx += 128) {
        int p = idx / RHv, u = idx % RHv;
        float v = r0s[u];
#pragma unroll
        for (int x = 0; x < 5; x++) v += cd[p][x] * R0s[x][u];
        h2s[p][u] = fmaxf(v, 0.f);
    }
    __syncthreads();

    if (t < NPAIR * 3) {
        int p = t / 3, y = t % 3;
        float v = r1s[y];
#pragma unroll
        for (int u = 0; u < RHv; u++) v += h2s[p][u] * R1s[u][y];
        if (y == 0) bp4s[p][0] = v;
        else if (y == 1) { bp4s[p][1] = v; bp4s[p][2] = v; }
        else bp4s[p][3] = v;
    }
    __syncthreads();

    int s = t;
    float accv = 0.f;
    int p = 0;
#pragma unroll
    for (int i = 0; i < NE; i++)
#pragma unroll
        for (int j = i + 1; j < NE; j++) {
            int bi = (s >> (6 - i)) & 1;
            int bj = (s >> (6 - j)) & 1;
            accv += bp4s[p][bi * 2 + bj];
            p++;
        }
    pairsum[(size_t)b * NCFG + s] = accv;
}

// ---------------- joint + lse + marginals: one warp per (n,b) -----------------
__global__ __launch_bounds__(256) void joint_kernel(
    const float* __restrict__ un, const float* __restrict__ ps,
    const float* __restrict__ b2v, float* __restrict__ out_marg,
    float* __restrict__ out_joint)
{
    int w = blockIdx.x * 8 + (threadIdx.x >> 5);
    int lane = threadIdx.x & 31;
    int b = w & (BSZv - 1), n = w >> 9;
    size_t nb = (size_t)n * BSZv + b;

    float val = 0.f;
    if (lane < 14) val = un[nb * 14 + lane] + b2v[lane & 1];
    float u[14];
#pragma unroll
    for (int i = 0; i < 14; i++) u[i] = __shfl_sync(0xffffffffu, val, i);

    float j[4], e[4];
    float mx = -1e30f;
#pragma unroll
    for (int q = 0; q < 4; q++) {
        int s = q * 32 + lane;
        float t = ps[(size_t)b * NCFG + s];
#pragma unroll
        for (int i = 0; i < NE; i++) t += u[i * 2 + ((s >> (6 - i)) & 1)];
        j[q] = t;
        mx = fmaxf(mx, t);
    }
#pragma unroll
    for (int o = 16; o; o >>= 1) mx = fmaxf(mx, __shfl_xor_sync(0xffffffffu, mx, o));

    float p1[NE], p0[NE];
#pragma unroll
    for (int i = 0; i < NE; i++) { p1[i] = 0.f; p0[i] = 0.f; }
#pragma unroll
    for (int q = 0; q < 4; q++) {
        int s = q * 32 + lane;
        e[q] = __expf(j[q] - mx);
#pragma unroll
        for (int i = 0; i < NE; i++) {
            if ((s >> (6 - i)) & 1) p1[i] += e[q];
            else p0[i] += e[q];
        }
    }
#pragma unroll
    for (int o = 16; o; o >>= 1)
#pragma unroll
        for (int i = 0; i < NE; i++) {
            p1[i] += __shfl_xor_sync(0xffffffffu, p1[i], o);
            p0[i] += __shfl_xor_sync(0xffffffffu, p0[i], o);
        }

    float lt = __logf(p1[0] + p0[0]);
#pragma unroll
    for (int q = 0; q < 4; q++)
        out_joint[nb * NCFG + q * 32 + lane] = j[q] - mx - lt;
    if (lane < NE)
        out_marg[nb * NE + lane] = __logf(p1[lane]) - __logf(p0[lane]);
}

// ---------------- launch -------------------------------------------------------
extern "C" void kernel_launch(void* const* d_in, const int* in_sizes, int n_in,
                              void* d_out, int out_size)
{
    const float* input = (const float*)d_in[0];
    const float* ctx   = (const float*)d_in[1];
    const float* W0 = (const float*)d_in[4];
    const float* b0 = (const float*)d_in[5];
    const float* W1 = (const float*)d_in[6];
    const float* b1 = (const float*)d_in[7];
    const float* W2 = (const float*)d_in[8];
    const float* b2 = (const float*)d_in[9];
    const float* R0 = (const float*)d_in[10];
    const float* r0 = (const float*)d_in[11];
    const float* R1 = (const float*)d_in[12];
    const float* r1 = (const float*)d_in[13];

    float* out = (float*)d_out;
    float* out_marg = out;
    float* out_joint = out + (size_t)M_ROWS;

    __half *w0p, *w1p, *h1p;
    float *un, *psum;
    cudaGetSymbolAddress((void**)&w0p, g_w0p);
    cudaGetSymbolAddress((void**)&w1p, g_w1p);
    cudaGetSymbolAddress((void**)&h1p, g_h1p);
    cudaGetSymbolAddress((void**)&un, g_un);
    cudaGetSymbolAddress((void**)&psum, g_pairsum);

    cudaFuncSetAttribute(gemm_tc<DIN, 0>, cudaFuncAttributeMaxDynamicSharedMemorySize, SMEM_SZ);
    cudaFuncSetAttribute(gemm_tc<DHv, 1>, cudaFuncAttributeMaxDynamicSharedMemorySize, SMEM_SZ);

    pack_weights<<<DIN, 256>>>(W0, w0p, DIN);
    pack_weights<<<DHv, 256>>>(W1, w1p, DHv);
    cudaMemsetAsync(un, 0, (size_t)M_ROWS * 2 * sizeof(float));

    gemm_tc<DIN, 0><<<PGRID, 256, SMEM_SZ>>>(
        input, nullptr, w0p, b0, nullptr, h1p, nullptr);
    gemm_tc<DHv, 1><<<PGRID, 256, SMEM_SZ>>>(
        nullptr, h1p, w1p, b1, W2, nullptr, un);
    binary_kernel<<<BSZv, 128>>>(ctx, R0, r0, R1, r1, psum);
    joint_kernel<<<(NN * BSZv) / 8, 256>>>(un, psum, b2, out_marg, out_joint);
}

// round 10
// speedup vs baseline: 1.8118x; 1.0943x over previous
#include <cuda_runtime.h>
#include <cuda_fp16.h>
#include <cstdint>
#include <math.h>

#define NN    32
#define BSZv  512
#define NE    7
#define DIN   512
#define DHv   256
#define RHv   64
#define NPAIR 21
#define M_ROWS (NN * BSZv * NE)   // 114688
#define NCFG  128
#define NTILES 1792
#define PGRID  304

// ---------------- scratch (device globals; no allocation allowed) ------------
__device__ __align__(128) __half g_w0p[(size_t)(DIN / 32) * DHv * 32];
__device__ __align__(128) __half g_w1p[(size_t)(DHv / 32) * DHv * 32];
__device__ __align__(128) __half g_h1p[(size_t)(DHv / 32) * M_ROWS * 32];
__device__ float g_un[(size_t)M_ROWS * 2];
__device__ float g_pairsum[(size_t)BSZv * NCFG];

// ---------------- PTX helpers ------------------------------------------------
__device__ __forceinline__ uint32_t smem_u32(const void* p) {
    uint32_t a;
    asm("{ .reg .u64 t; cvta.to.shared.u64 t, %1; cvt.u32.u64 %0, t; }" : "=r"(a) : "l"(p));
    return a;
}
__device__ __forceinline__ void ldsm4(uint32_t a, uint32_t* r) {
    asm volatile("ldmatrix.sync.aligned.m8n8.x4.shared.b16 {%0,%1,%2,%3}, [%4];"
                 : "=r"(r[0]), "=r"(r[1]), "=r"(r[2]), "=r"(r[3]) : "r"(a));
}
__device__ __forceinline__ void mma_f16(float* c, const uint32_t* a, uint32_t b0, uint32_t b1) {
    asm volatile("mma.sync.aligned.m16n8k16.row.col.f32.f16.f16.f32 "
                 "{%0,%1,%2,%3}, {%4,%5,%6,%7}, {%8,%9}, {%0,%1,%2,%3};"
                 : "+f"(c[0]), "+f"(c[1]), "+f"(c[2]), "+f"(c[3])
                 : "r"(a[0]), "r"(a[1]), "r"(a[2]), "r"(a[3]), "r"(b0), "r"(b1));
}
#define CP16(dst, src) asm volatile("cp.async.cg.shared.global [%0], [%1], 16;" :: "r"(dst), "l"(src))
#define CPCOMMIT()     asm volatile("cp.async.commit_group;" ::: "memory")
#define CPWAIT1()      asm volatile("cp.async.wait_group 1;" ::: "memory")
#define STS128(a, v0, v1, v2, v3) \
    asm volatile("st.shared.v4.b32 [%0], {%1,%2,%3,%4};" :: "r"(a), "r"(v0), "r"(v1), "r"(v2), "r"(v3))

__device__ __forceinline__ uint32_t pack2h(__half a, __half b) {
    __half2 t = __halves2half2(a, b);
    return *reinterpret_cast<uint32_t*>(&t);
}

// ---------------- weight packing ----------------------------------------------
__global__ __launch_bounds__(256) void pack_weights(
    const float* __restrict__ W, __half* __restrict__ dst, int K)
{
    int idx = blockIdx.x * 256 + threadIdx.x;
    if (idx >= K * 256) return;
    int k = idx >> 8, n = idx & 255;
    size_t o = ((size_t)(k >> 5) * 256 + n) * 32 + (k & 31);
    dst[o] = __float2half_rn(W[idx]);
}

// ---------------- GEMM (fp16 mma, persistent, B-resident) ----------------------
// SMEM: [0,64K) resident B: 4 pair-regions 16KB (chunks 2p: groups 0-3, 2p+1: 4-7)
//       [64K,80K) A region, parity-packed double buffer
//       [80K,96K) B stream region (MODE0 chunks>=8), parity-packed
#define RES_OFF 0
#define A_OFF   65536
#define BS_OFF  81920
#define SM_BIAS 98304
#define SM_W2   99328
#define SMEM_SZ 101376

template <int KDIM, int MODE>
__global__ __launch_bounds__(256, 2) void gemm_tc(
    const float* __restrict__ Af, const __half* __restrict__ Ap,
    const __half* __restrict__ Wp, const float* __restrict__ bias,
    const float* __restrict__ W2, __half* __restrict__ outp,
    float* __restrict__ un)
{
    extern __shared__ char smem[];
    constexpr int NC = KDIM / 32;
    const int tid = threadIdx.x;
    const int lane = tid & 31;
    const int wid = tid >> 5;
    const int warp_m = wid >> 2, warp_n = wid & 3;
    const int bid = blockIdx.x;
    const int GRID = gridDim.x;
    const int nB = (bid & 1) * 128;          // fixed n-half per CTA (GRID even)

    const uint32_t sb = smem_u32(smem);
    float* biasS = (float*)(smem + SM_BIAS);
    float* W2s = (float*)(smem + SM_W2);
    biasS[tid] = bias[tid];
    if (MODE == 1) { W2s[tid] = W2[tid]; W2s[tid + 256] = W2[tid + 256]; }

    const int crow = tid >> 1;
    const int chalf = tid & 1;
    const int cxor = crow & 7;

    const uint32_t aRowOff = (uint32_t)(warp_m * 64 + (lane & 15)) * 128;
    const uint32_t aKsel = (uint32_t)(lane >> 4);
    const uint32_t bRowOff = (uint32_t)(warp_n * 32 + ((lane >> 4) << 3) + (lane & 7)) * 128;
    const uint32_t bKsel = (uint32_t)((lane >> 3) & 1);
    const uint32_t xr = (uint32_t)(lane & 7);

    const int myTiles = (NTILES - bid + GRID - 1) / GRID;
    const int total = myTiles * NC;

    float acc[4][4][4];
#pragma unroll
    for (int a = 0; a < 4; a++)
#pragma unroll
        for (int b = 0; b < 4; b++)
#pragma unroll
            for (int q = 0; q < 4; q++) acc[a][b][q] = 0.f;

    float rA[16];   // MODE0 staging

    // ---- resident B: chunks 0..min(NC,8)-1 of this CTA's n-half, one-time ----
    {
#pragma unroll
        for (int p = 0; p < 4; p++) {
            int c = 2 * p + chalf;
            const char* src = (const char*)(Wp + ((size_t)c * 256 + nB + crow) * 32);
            uint32_t dst = sb + RES_OFF + p * 16384 + crow * 128;
#pragma unroll
            for (int j = 0; j < 4; j++)
                CP16(dst + ((uint32_t)(4 * chalf + j) ^ cxor) * 16, src + j * 16);
        }
        CPCOMMIT();
    }

    auto loadA_regs = [&](int s) {            // MODE0 only
        int i = s / NC, c = s % NC;
        int t = bid + i * GRID;
        size_t mB = (size_t)(t >> 1) * 128;
        const float* p = Af + (mB + crow) * KDIM + c * 32 + chalf * 16;
        *(float4*)(rA)      = *(const float4*)(p);
        *(float4*)(rA + 4)  = *(const float4*)(p + 4);
        *(float4*)(rA + 8)  = *(const float4*)(p + 8);
        *(float4*)(rA + 12) = *(const float4*)(p + 12);
    };
    auto storeA_regs = [&](int par) {
        uint32_t dst = sb + A_OFF + crow * 128;
        uint32_t hh[8];
#pragma unroll
        for (int q = 0; q < 8; q++)
            hh[q] = pack2h(__float2half_rn(rA[2 * q]), __float2half_rn(rA[2 * q + 1]));
        STS128(dst + ((uint32_t)(4 * par + 2 * chalf + 0) ^ cxor) * 16, hh[0], hh[1], hh[2], hh[3]);
        STS128(dst + ((uint32_t)(4 * par + 2 * chalf + 1) ^ cxor) * 16, hh[4], hh[5], hh[6], hh[7]);
    };
    auto prefetch = [&](int ss) {
        if (ss < total) {
            int c = ss % NC;
            int par = ss & 1;
            if (MODE == 1) {
                int i = ss / NC;
                int t = bid + i * GRID;
                size_t mB = (size_t)(t >> 1) * 128;
                const char* srcA = (const char*)(Ap + ((size_t)c * M_ROWS + mB + crow) * 32 + chalf * 16);
                uint32_t dstA = sb + A_OFF + crow * 128;
#pragma unroll
                for (int j = 0; j < 2; j++)
                    CP16(dstA + ((uint32_t)(4 * par + 2 * chalf + j) ^ cxor) * 16, srcA + j * 16);
            } else if (c >= 8) {
                const char* srcB = (const char*)(Wp + ((size_t)c * 256 + nB + crow) * 32 + chalf * 16);
                uint32_t dstB = sb + BS_OFF + crow * 128;
#pragma unroll
                for (int j = 0; j < 2; j++)
                    CP16(dstB + ((uint32_t)(4 * par + 2 * chalf + j) ^ cxor) * 16, srcB + j * 16);
            }
        }
        CPCOMMIT();
    };
    auto compute = [&](int sidx) {
        int c = sidx % NC;
        uint32_t gb = 4u * (uint32_t)(sidx & 1);
        uint32_t Ab = sb + A_OFF + aRowOff;
        uint32_t Bb = (MODE == 0 && c >= 8) ? (sb + BS_OFF + bRowOff)
                                            : (sb + RES_OFF + (uint32_t)(c >> 1) * 16384 + bRowOff);
#pragma unroll
        for (int ks = 0; ks < 2; ks++) {
            uint32_t bh[8];
            ldsm4(Bb + ((gb + 2 * ks + bKsel) ^ xr) * 16, bh);
            ldsm4(Bb + 2048 + ((gb + 2 * ks + bKsel) ^ xr) * 16, bh + 4);
#pragma unroll
            for (int mi = 0; mi < 4; mi++) {
                uint32_t ah[4];
                ldsm4(Ab + mi * 2048 + ((gb + 2 * ks + aKsel) ^ xr) * 16, ah);
#pragma unroll
                for (int nj = 0; nj < 4; nj++)
                    mma_f16(acc[mi][nj], ah, bh[2 * nj], bh[2 * nj + 1]);
            }
        }
    };

    const int rloc = warp_m * 64 + (lane >> 2);
    const int nl0 = warp_n * 32 + (lane & 3) * 2;

    // ---- prologue ----
    prefetch(0);
    if (MODE == 0) {
        loadA_regs(0); storeA_regs(0);
        if (total > 1) { loadA_regs(1); storeA_regs(1); }
        if (total > 2) loadA_regs(2);
    }

    // ---- main loop ----
    for (int s = 0; s < total; s++) {
        prefetch(s + 1);
        CPWAIT1();
        __syncthreads();
        compute(s);

        if ((s % NC) == NC - 1) {
            const int t = bid + (s / NC) * GRID;
            const size_t mBase = (size_t)(t >> 1) * 128;
            if (MODE == 0) {
#pragma unroll
                for (int mi = 0; mi < 4; mi++)
#pragma unroll
                    for (int nj = 0; nj < 4; nj++) {
                        int nl = nl0 + nj * 8;
                        float b0v = biasS[nB + nl], b1v = biasS[nB + nl + 1];
                        float v00 = fmaxf(acc[mi][nj][0] + b0v, 0.f);
                        float v01 = fmaxf(acc[mi][nj][1] + b1v, 0.f);
                        float v10 = fmaxf(acc[mi][nj][2] + b0v, 0.f);
                        float v11 = fmaxf(acc[mi][nj][3] + b1v, 0.f);
                        int gn = nB + nl;
                        int cpk = gn >> 5, slot = gn & 31;
                        size_t r0 = mBase + rloc + mi * 16;
                        size_t o0 = ((size_t)cpk * M_ROWS + r0) * 32 + slot;
                        size_t o1 = o0 + 8 * 32;
                        *(uint32_t*)(outp + o0) =
                            pack2h(__float2half_rn(v00), __float2half_rn(v01));
                        *(uint32_t*)(outp + o1) =
                            pack2h(__float2half_rn(v10), __float2half_rn(v11));
                        acc[mi][nj][0] = 0.f; acc[mi][nj][1] = 0.f;
                        acc[mi][nj][2] = 0.f; acc[mi][nj][3] = 0.f;
                    }
            } else {
                float up[16];
#pragma unroll
                for (int i = 0; i < 16; i++) up[i] = 0.f;
#pragma unroll
                for (int mi = 0; mi < 4; mi++)
#pragma unroll
                    for (int nj = 0; nj < 4; nj++) {
                        int nl = nl0 + nj * 8;
                        float b0v = biasS[nB + nl], b1v = biasS[nB + nl + 1];
                        float w00 = W2s[2 * (nB + nl)],     w01 = W2s[2 * (nB + nl) + 1];
                        float w10 = W2s[2 * (nB + nl) + 2], w11 = W2s[2 * (nB + nl) + 3];
                        float v00 = fmaxf(acc[mi][nj][0] + b0v, 0.f);
                        float v01 = fmaxf(acc[mi][nj][1] + b1v, 0.f);
                        float v10 = fmaxf(acc[mi][nj][2] + b0v, 0.f);
                        float v11 = fmaxf(acc[mi][nj][3] + b1v, 0.f);
                        up[mi * 4 + 0] += v00 * w00 + v01 * w10;
                        up[mi * 4 + 1] += v00 * w01 + v01 * w11;
                        up[mi * 4 + 2] += v10 * w00 + v11 * w10;
                        up[mi * 4 + 3] += v10 * w01 + v11 * w11;
                        acc[mi][nj][0] = 0.f; acc[mi][nj][1] = 0.f;
                        acc[mi][nj][2] = 0.f; acc[mi][nj][3] = 0.f;
                    }
#pragma unroll
                for (int k = 1; k <= 2; k <<= 1)
#pragma unroll
                    for (int i = 0; i < 16; i++)
                        up[i] += __shfl_xor_sync(0xffffffffu, up[i], k);
                if ((lane & 3) == 0) {
#pragma unroll
                    for (int mi = 0; mi < 4; mi++) {
                        size_t r0 = mBase + rloc + mi * 16;
                        size_t r1 = r0 + 8;
                        atomicAdd(&un[r0 * 2 + 0], up[mi * 4 + 0]);
                        atomicAdd(&un[r0 * 2 + 1], up[mi * 4 + 1]);
                        atomicAdd(&un[r1 * 2 + 0], up[mi * 4 + 2]);
                        atomicAdd(&un[r1 * 2 + 1], up[mi * 4 + 3]);
                    }
                }
            }
        }

        __syncthreads();   // guards parity-region reuse (WAR) for next prefetch/STS

        if (MODE == 0) {
            if (s + 2 < total) {
                storeA_regs((s + 2) & 1);
                if (s + 3 < total) loadA_regs(s + 3);
            }
        }
    }
}

// -------- binary MLP + pairwise config sums ----------------------------------
__global__ __launch_bounds__(128) void binary_kernel(
    const float* __restrict__ ctx, const float* __restrict__ R0,
    const float* __restrict__ r0, const float* __restrict__ R1,
    const float* __restrict__ r1, float* __restrict__ pairsum)
{
    __shared__ float cd[NPAIR][5];
    __shared__ float R0s[5][RHv];
    __shared__ float r0s[RHv];
    __shared__ float R1s[RHv][3];
    __shared__ float r1s[3];
    __shared__ float h2s[NPAIR][RHv];
    __shared__ float bp4s[NPAIR][4];

    int b = blockIdx.x, t = threadIdx.x;
    for (int i = t; i < NPAIR * 5; i += 128) cd[i / 5][i % 5] = ctx[b * NPAIR * 5 + i];
    for (int i = t; i < 5 * RHv; i += 128) R0s[i / RHv][i % RHv] = R0[i];
    if (t < RHv) r0s[t] = r0[t];
    for (int i = t; i < RHv * 3; i += 128) R1s[i / 3][i % 3] = R1[i];
    if (t < 3) r1s[t] = r1[t];
    __syncthreads();

    for (int idx = t; idx < NPAIR * RHv; idx += 128) {
        int p = idx / RHv, u = idx % RHv;
        float v = r0s[u];
#pragma unroll
        for (int x = 0; x < 5; x++) v += cd[p][x] * R0s[x][u];
        h2s[p][u] = fmaxf(v, 0.f);
    }
    __syncthreads();

    if (t < NPAIR * 3) {
        int p = t / 3, y = t % 3;
        float v = r1s[y];
#pragma unroll
        for (int u = 0; u < RHv; u++) v += h2s[p][u] * R1s[u][y];
        if (y == 0) bp4s[p][0] = v;
        else if (y == 1) { bp4s[p][1] = v; bp4s[p][2] = v; }
        else bp4s[p][3] = v;
    }
    __syncthreads();

    int s = t;
    float accv = 0.f;
    int p = 0;
#pragma unroll
    for (int i = 0; i < NE; i++)
#pragma unroll
        for (int j = i + 1; j < NE; j++) {
            int bi = (s >> (6 - i)) & 1;
            int bj = (s >> (6 - j)) & 1;
            accv += bp4s[p][bi * 2 + bj];
            p++;
        }
    pairsum[(size_t)b * NCFG + s] = accv;
}

// ---------------- joint + lse + marginals: one warp per (n,b) -----------------
__global__ __launch_bounds__(256) void joint_kernel(
    const float* __restrict__ un, const float* __restrict__ ps,
    const float* __restrict__ b2v, float* __restrict__ out_marg,
    float* __restrict__ out_joint)
{
    int w = blockIdx.x * 8 + (threadIdx.x >> 5);
    int lane = threadIdx.x & 31;
    int b = w & (BSZv - 1), n = w >> 9;
    size_t nb = (size_t)n * BSZv + b;

    float val = 0.f;
    if (lane < 14) val = un[nb * 14 + lane] + b2v[lane & 1];
    float u[14];
#pragma unroll
    for (int i = 0; i < 14; i++) u[i] = __shfl_sync(0xffffffffu, val, i);

    float j[4], e[4];
    float mx = -1e30f;
#pragma unroll
    for (int q = 0; q < 4; q++) {
        int s = q * 32 + lane;
        float t = ps[(size_t)b * NCFG + s];
#pragma unroll
        for (int i = 0; i < NE; i++) t += u[i * 2 + ((s >> (6 - i)) & 1)];
        j[q] = t;
        mx = fmaxf(mx, t);
    }
#pragma unroll
    for (int o = 16; o; o >>= 1) mx = fmaxf(mx, __shfl_xor_sync(0xffffffffu, mx, o));

    float p1[NE], p0[NE];
#pragma unroll
    for (int i = 0; i < NE; i++) { p1[i] = 0.f; p0[i] = 0.f; }
#pragma unroll
    for (int q = 0; q < 4; q++) {
        int s = q * 32 + lane;
        e[q] = __expf(j[q] - mx);
#pragma unroll
        for (int i = 0; i < NE; i++) {
            if ((s >> (6 - i)) & 1) p1[i] += e[q];
            else p0[i] += e[q];
        }
    }
#pragma unroll
    for (int o = 16; o; o >>= 1)
#pragma unroll
        for (int i = 0; i < NE; i++) {
            p1[i] += __shfl_xor_sync(0xffffffffu, p1[i], o);
            p0[i] += __shfl_xor_sync(0xffffffffu, p0[i], o);
        }

    float lt = __logf(p1[0] + p0[0]);
#pragma unroll
    for (int q = 0; q < 4; q++)
        out_joint[nb * NCFG + q * 32 + lane] = j[q] - mx - lt;
    if (lane < NE)
        out_marg[nb * NE + lane] = __logf(p1[lane]) - __logf(p0[lane]);
}

// ---------------- launch -------------------------------------------------------
extern "C" void kernel_launch(void* const* d_in, const int* in_sizes, int n_in,
                              void* d_out, int out_size)
{
    const float* input = (const float*)d_in[0];
    const float* ctx   = (const float*)d_in[1];
    const float* W0 = (const float*)d_in[4];
    const float* b0 = (const float*)d_in[5];
    const float* W1 = (const float*)d_in[6];
    const float* b1 = (const float*)d_in[7];
    const float* W2 = (const float*)d_in[8];
    const float* b2 = (const float*)d_in[9];
    const float* R0 = (const float*)d_in[10];
    const float* r0 = (const float*)d_in[11];
    const float* R1 = (const float*)d_in[12];
    const float* r1 = (const float*)d_in[13];

    float* out = (float*)d_out;
    float* out_marg = out;
    float* out_joint = out + (size_t)M_ROWS;

    __half *w0p, *w1p, *h1p;
    float *un, *psum;
    cudaGetSymbolAddress((void**)&w0p, g_w0p);
    cudaGetSymbolAddress((void**)&w1p, g_w1p);
    cudaGetSymbolAddress((void**)&h1p, g_h1p);
    cudaGetSymbolAddress((void**)&un, g_un);
    cudaGetSymbolAddress((void**)&psum, g_pairsum);

    cudaFuncSetAttribute(gemm_tc<DIN, 0>, cudaFuncAttributeMaxDynamicSharedMemorySize, SMEM_SZ);
    cudaFuncSetAttribute(gemm_tc<DHv, 1>, cudaFuncAttributeMaxDynamicSharedMemorySize, SMEM_SZ);

    pack_weights<<<DIN, 256>>>(W0, w0p, DIN);
    pack_weights<<<DHv, 256>>>(W1, w1p, DHv);
    cudaMemsetAsync(un, 0, (size_t)M_ROWS * 2 * sizeof(float));

    gemm_tc<DIN, 0><<<PGRID, 256, SMEM_SZ>>>(
        input, nullptr, w0p, b0, nullptr, h1p, nullptr);
    gemm_tc<DHv, 1><<<PGRID, 256, SMEM_SZ>>>(
        nullptr, h1p, w1p, b1, W2, nullptr, un);
    binary_kernel<<<BSZv, 128>>>(ctx, R0, r0, R1, r1, psum);
    joint_kernel<<<(NN * BSZv) / 8, 256>>>(un, psum, b2, out_marg, out_joint);
}